// round 2
// baseline (speedup 1.0000x reference)
#include <cuda_runtime.h>
#include <math.h>

#define B_ 384
#define Q_ 384
#define V_ 197
#define T_ 100
#define D_ 768
#define E_ 256
#define K_ 50
#define QT 8
#define VROW 260   // 256 + 4 pad: breaks the stride-256 (=0 mod 32 banks) conflict

// ---------------- scratch (no allocations allowed) ----------------
__device__ float  g_vtok[B_*V_*E_];   // projected (then normalized in-place) visual tokens
__device__ float  g_ttok[Q_*T_*E_];   // projected (then normalized in-place) textual tokens
__device__ float  g_vglob[B_*E_];
__device__ float  g_tglob[Q_*E_];
__device__ double g_vsim[B_*V_];
__device__ double g_tsim[Q_*T_];
__device__ int    g_iv[B_*K_];
__device__ int    g_it[Q_*K_];

// ---------------- GEMM + bias: C[M,256] = A[M,768] @ W[768,256] + b ----------------
// 64x64 tile, BK=16, 256 threads, 4x4 register tile. All M are multiples of 64.
__global__ void gemm_bias_kernel(const float* __restrict__ A, const float* __restrict__ W,
                                 const float* __restrict__ bias, float* __restrict__ C) {
    __shared__ __align__(16) float Ast[16][64];  // k-major
    __shared__ __align__(16) float Bs[16][64];
    const int tid = threadIdx.x;
    const int tx = tid & 15, ty = tid >> 4;
    const int m0 = blockIdx.y * 64, n0 = blockIdx.x * 64;
    const int arow = tid & 63, ak4 = (tid >> 6) << 2;
    const int bk = tid >> 4, bn4 = (tid & 15) << 2;
    float acc[4][4] = {};
    for (int k0 = 0; k0 < D_; k0 += 16) {
        float4 av = *reinterpret_cast<const float4*>(A + (size_t)(m0 + arow) * D_ + k0 + ak4);
        Ast[ak4 + 0][arow] = av.x; Ast[ak4 + 1][arow] = av.y;
        Ast[ak4 + 2][arow] = av.z; Ast[ak4 + 3][arow] = av.w;
        *reinterpret_cast<float4*>(&Bs[bk][bn4]) =
            *reinterpret_cast<const float4*>(W + (size_t)(k0 + bk) * E_ + n0 + bn4);
        __syncthreads();
#pragma unroll
        for (int kk = 0; kk < 16; kk++) {
            float4 a4 = *reinterpret_cast<const float4*>(&Ast[kk][ty * 4]);
            float4 b4 = *reinterpret_cast<const float4*>(&Bs[kk][tx * 4]);
            float af[4] = {a4.x, a4.y, a4.z, a4.w};
            float bf[4] = {b4.x, b4.y, b4.z, b4.w};
#pragma unroll
            for (int i = 0; i < 4; i++)
#pragma unroll
                for (int j = 0; j < 4; j++) acc[i][j] += af[i] * bf[j];
        }
        __syncthreads();
    }
#pragma unroll
    for (int i = 0; i < 4; i++) {
        int row = m0 + ty * 4 + i;
#pragma unroll
        for (int j = 0; j < 4; j++) {
            int col = n0 + tx * 4 + j;
            C[(size_t)row * E_ + col] = acc[i][j] + bias[col];
        }
    }
}

// ---------------- l2-normalize rows of [n,256] -> out (f64 norm, f32 division) ----------------
__global__ void norm_rows_kernel(const float* __restrict__ in, float* __restrict__ out, int nrows) {
    int warp = (blockIdx.x * blockDim.x + threadIdx.x) >> 5;
    int lane = threadIdx.x & 31;
    if (warp >= nrows) return;
    const float* r = in + (size_t)warp * E_;
    float v[8]; double s = 0.0;
#pragma unroll
    for (int j = 0; j < 8; j++) { v[j] = r[j * 32 + lane]; s += (double)v[j] * (double)v[j]; }
#pragma unroll
    for (int o = 16; o > 0; o >>= 1) s += __shfl_xor_sync(0xffffffffu, s, o);
    float nf = fmaxf((float)sqrt(s), 1e-12f);
#pragma unroll
    for (int j = 0; j < 8; j++) out[(size_t)warp * E_ + j * 32 + lane] = v[j] / nf;
}

// -------- normalize token rows in-place (f64 norm, f32 div) + f64 dot with global --------
__global__ void norm_tok_sim_kernel(float* __restrict__ tok, const float* __restrict__ glob,
                                    double* __restrict__ sim, int nrows, int tokens_per_item) {
    int warp = (blockIdx.x * blockDim.x + threadIdx.x) >> 5;
    int lane = threadIdx.x & 31;
    if (warp >= nrows) return;
    float* r = tok + (size_t)warp * E_;
    float v[8]; double s = 0.0;
#pragma unroll
    for (int j = 0; j < 8; j++) { v[j] = r[j * 32 + lane]; s += (double)v[j] * (double)v[j]; }
#pragma unroll
    for (int o = 16; o > 0; o >>= 1) s += __shfl_xor_sync(0xffffffffu, s, o);
    float nf = fmaxf((float)sqrt(s), 1e-12f);
    const float* g = glob + (size_t)(warp / tokens_per_item) * E_;
    double d = 0.0;
#pragma unroll
    for (int j = 0; j < 8; j++) {
        float nv = v[j] / nf;              // f32 division: matches reference rounding
        r[j * 32 + lane] = nv;
        d += (double)nv * (double)g[j * 32 + lane];   // exact ranking key
    }
#pragma unroll
    for (int o = 16; o > 0; o >>= 1) d += __shfl_xor_sync(0xffffffffu, d, o);
    if (lane == 0) sim[warp] = d;
}

// ---------------- top-K (K=50) per item, descending, lowest-index tie-break ----------------
__global__ void topk_kernel(const double* __restrict__ sim, int* __restrict__ out, int n) {
    __shared__ double vals[256];
    __shared__ double wv[8];
    __shared__ int wi[8];
    int b = blockIdx.x;
    int t = threadIdx.x;
    vals[t] = (t < n) ? sim[(size_t)b * n + t] : -1e300;
    __syncthreads();
    for (int k = 0; k < K_; k++) {
        double v = vals[t]; int i = t;
#pragma unroll
        for (int o = 16; o > 0; o >>= 1) {
            double ov = __shfl_xor_sync(0xffffffffu, v, o);
            int oi = __shfl_xor_sync(0xffffffffu, i, o);
            if (ov > v || (ov == v && oi < i)) { v = ov; i = oi; }
        }
        if ((t & 31) == 0) { wv[t >> 5] = v; wi[t >> 5] = i; }
        __syncthreads();
        if (t == 0) {
            double bv = wv[0]; int bi = wi[0];
#pragma unroll
            for (int w = 1; w < 8; w++)
                if (wv[w] > bv || (wv[w] == bv && wi[w] < bi)) { bv = wv[w]; bi = wi[w]; }
            out[b * K_ + k] = bi;
            vals[bi] = -1e300;
        }
        __syncthreads();
    }
}

// ---------------- gather selected normalized tokens into output ----------------
__global__ void gather_kernel(const float* __restrict__ tok, const int* __restrict__ idx,
                              float* __restrict__ outp, int tokens_per_item) {
    int bk = blockIdx.x;
    int item = bk / K_;
    int src = idx[bk];
    const float4* s = reinterpret_cast<const float4*>(tok + ((size_t)item * tokens_per_item + src) * E_);
    float4* d = reinterpret_cast<float4*>(outp + (size_t)bk * E_);
    d[threadIdx.x] = s[threadIdx.x];   // 64 threads x float4 = 256 floats
}

// ---------------- fused cross-modal sim + max/mean reductions ----------------
// One block per (b, 8 q's). v_loc[b] (50x256) persistent in smem; per q load t_loc[q],
// compute the 50x50 Gram tile (250 threads, 5x2 register tiles), reduce row/col maxes.
__global__ void cross_sim_kernel(const float* __restrict__ vloc, const float* __restrict__ tloc,
                                 float* __restrict__ i2t, float* __restrict__ t2i) {
    extern __shared__ __align__(16) float sm[];
    float* vsm = sm;                    // 50*VROW
    float* tsm = sm + 50 * VROW;        // 50*VROW
    float* ssm = sm + 100 * VROW;       // 2500
    float* redA = ssm + 2500;           // 50 row maxes (per v)
    float* redB = redA + 50;            // 50 col maxes (per t)
    const int b = blockIdx.y;
    const int q0 = blockIdx.x * QT;
    const int t = threadIdx.x;
    {
        const float4* src = reinterpret_cast<const float4*>(vloc + (size_t)b * K_ * E_);
        for (int i = t; i < K_ * E_ / 4; i += 256) {
            int row = i >> 6, c4 = i & 63;
            *reinterpret_cast<float4*>(&vsm[row * VROW + c4 * 4]) = src[i];
        }
    }
    const int ii = t % 10;   // row group (5 rows each)
    const int jj = t / 10;   // col group (2 cols each)
    for (int qi = 0; qi < QT; qi++) {
        int q = q0 + qi;
        __syncthreads();
        {
            const float4* src = reinterpret_cast<const float4*>(tloc + (size_t)q * K_ * E_);
            for (int i = t; i < K_ * E_ / 4; i += 256) {
                int row = i >> 6, c4 = i & 63;
                *reinterpret_cast<float4*>(&tsm[row * VROW + c4 * 4]) = src[i];
            }
        }
        __syncthreads();
        if (t < 250) {
            float acc[5][2] = {};
            const float* a0 = &vsm[(ii * 5) * VROW];
            const float* b0 = &tsm[(jj * 2) * VROW];
#pragma unroll 4
            for (int k = 0; k < E_; k += 4) {
                float4 bb0 = *reinterpret_cast<const float4*>(&b0[k]);
                float4 bb1 = *reinterpret_cast<const float4*>(&b0[VROW + k]);
#pragma unroll
                for (int r = 0; r < 5; r++) {
                    float4 aa = *reinterpret_cast<const float4*>(&a0[r * VROW + k]);
                    acc[r][0] += aa.x * bb0.x + aa.y * bb0.y + aa.z * bb0.z + aa.w * bb0.w;
                    acc[r][1] += aa.x * bb1.x + aa.y * bb1.y + aa.z * bb1.z + aa.w * bb1.w;
                }
            }
#pragma unroll
            for (int r = 0; r < 5; r++) {
                ssm[(ii * 5 + r) * 50 + jj * 2 + 0] = acc[r][0];
                ssm[(ii * 5 + r) * 50 + jj * 2 + 1] = acc[r][1];
            }
        }
        __syncthreads();
        if (t < 50) {
            float rm = -1e30f, cm = -1e30f;
            for (int c = 0; c < 50; c++) {
                rm = fmaxf(rm, ssm[t * 50 + c]);   // max over t-cols  (i2t, per v-row)
                cm = fmaxf(cm, ssm[c * 50 + t]);   // max over v-rows  (t2i, per t-col)
            }
            redA[t] = rm; redB[t] = cm;
        }
        __syncthreads();
        if (t == 0) {
            float s = 0.f;
            for (int c = 0; c < 50; c++) s += redA[c];
            i2t[(size_t)b * Q_ + q] = s * (1.0f / 50.0f);
        } else if (t == 32) {
            float s = 0.f;
            for (int c = 0; c < 50; c++) s += redB[c];
            t2i[(size_t)b * Q_ + q] = s * (1.0f / 50.0f);
        }
    }
}

// ---------------- launch ----------------
extern "C" void kernel_launch(void* const* d_in, const int* in_sizes, int n_in,
                              void* d_out, int out_size) {
    const float* visual_cls     = (const float*)d_in[0];
    const float* visual_tokens  = (const float*)d_in[1];
    const float* textual_cls    = (const float*)d_in[2];
    const float* textual_tokens = (const float*)d_in[3];
    const float* Wv     = (const float*)d_in[4];
    const float* bv     = (const float*)d_in[5];
    const float* Wt     = (const float*)d_in[6];
    const float* bt     = (const float*)d_in[7];
    const float* Wv_tok = (const float*)d_in[8];
    const float* bv_tok = (const float*)d_in[9];
    const float* Wt_tok = (const float*)d_in[10];
    const float* bt_tok = (const float*)d_in[11];

    float* out = (float*)d_out;
    float* o_vcls = out;                       // [384,256]
    float* o_tcls = o_vcls + B_ * E_;          // [384,256]
    float* o_vloc = o_tcls + Q_ * E_;          // [384,50,256]
    float* o_tloc = o_vloc + B_ * K_ * E_;     // [384,50,256]
    float* o_i2t  = o_tloc + Q_ * K_ * E_;     // [384,384]
    float* o_t2i  = o_i2t + B_ * Q_;           // [384,384]

    float *p_vtok, *p_ttok, *p_vglob, *p_tglob;
    double *p_vsim, *p_tsim;
    int *p_iv, *p_it;
    cudaGetSymbolAddress((void**)&p_vtok, g_vtok);
    cudaGetSymbolAddress((void**)&p_ttok, g_ttok);
    cudaGetSymbolAddress((void**)&p_vglob, g_vglob);
    cudaGetSymbolAddress((void**)&p_tglob, g_tglob);
    cudaGetSymbolAddress((void**)&p_vsim, g_vsim);
    cudaGetSymbolAddress((void**)&p_tsim, g_tsim);
    cudaGetSymbolAddress((void**)&p_iv, g_iv);
    cudaGetSymbolAddress((void**)&p_it, g_it);

    // projections
    gemm_bias_kernel<<<dim3(E_ / 64, B_ / 64), 256>>>(visual_cls, Wv, bv, o_vcls);
    gemm_bias_kernel<<<dim3(E_ / 64, Q_ / 64), 256>>>(textual_cls, Wt, bt, o_tcls);
    gemm_bias_kernel<<<dim3(E_ / 64, (B_ * V_) / 64), 256>>>(visual_tokens, Wv_tok, bv_tok, p_vtok);
    gemm_bias_kernel<<<dim3(E_ / 64, (Q_ * T_) / 64), 256>>>(textual_tokens, Wt_tok, bt_tok, p_ttok);

    // cls normalization (v_cls/t_cls outputs stay un-normalized)
    norm_rows_kernel<<<(B_ * 32) / 256, 256>>>(o_vcls, p_vglob, B_);
    norm_rows_kernel<<<(Q_ * 32) / 256, 256>>>(o_tcls, p_tglob, Q_);

    // token normalize (in place) + token->cls similarity (f64 ranking keys)
    norm_tok_sim_kernel<<<(B_ * V_ * 32) / 256, 256>>>(p_vtok, p_vglob, p_vsim, B_ * V_, V_);
    norm_tok_sim_kernel<<<(Q_ * T_ * 32) / 256, 256>>>(p_ttok, p_tglob, p_tsim, Q_ * T_, T_);

    // top-K selection + gather into outputs
    topk_kernel<<<B_, 256>>>(p_vsim, p_iv, V_);
    topk_kernel<<<Q_, 256>>>(p_tsim, p_it, T_);
    gather_kernel<<<B_ * K_, 64>>>(p_vtok, p_iv, o_vloc, V_);
    gather_kernel<<<Q_ * K_, 64>>>(p_ttok, p_it, o_tloc, T_);

    // fused all-pairs cross-modal sim + max/mean
    const int SMEM = (100 * VROW + 2500 + 100) * 4;  // 114,400 B
    cudaFuncSetAttribute(cross_sim_kernel, cudaFuncAttributeMaxDynamicSharedMemorySize, SMEM);
    cross_sim_kernel<<<dim3(Q_ / QT, B_), 256, SMEM>>>(o_vloc, o_tloc, o_i2t, o_t2i);
}

// round 4
// speedup vs baseline: 2.3589x; 2.3589x over previous
#include <cuda_runtime.h>
#include <cuda_bf16.h>
#include <math.h>
#include <stdint.h>

#define B_ 384
#define Q_ 384
#define V_ 197
#define T_ 100
#define D_ 768
#define E_ 256
#define K_ 50
#define KP 64            // padded tokens per item
#define MR (B_ * KP)     // 24576 padded rows per side

// ---------------- scratch (no allocations allowed) ----------------
__device__ float  g_vtok[B_*V_*E_];
__device__ float  g_ttok[Q_*T_*E_];
__device__ float  g_vglob[B_*E_];
__device__ float  g_tglob[Q_*E_];
__device__ double g_vsim[B_*V_];
__device__ double g_tsim[Q_*T_];
__device__ int    g_iv[B_*K_];
__device__ int    g_it[Q_*K_];
__device__ __nv_bfloat16 g_vhi[MR*E_];
__device__ __nv_bfloat16 g_vlo[MR*E_];
__device__ __nv_bfloat16 g_thi[MR*E_];
__device__ __nv_bfloat16 g_tlo[MR*E_];

// ================= PTX helpers (baseline ISA only — no tcgen05 at compute_103) ==========
__device__ __forceinline__ uint32_t smem_u32(const void* p) {
    uint32_t a;
    asm("{ .reg .u64 t; cvta.to.shared.u64 t, %1; cvt.u32.u64 %0, t; }" : "=r"(a) : "l"(p));
    return a;
}
__device__ __forceinline__ void ldsm_x4(uint32_t* r, uint32_t addr) {
    asm volatile("ldmatrix.sync.aligned.m8n8.x4.shared.b16 {%0,%1,%2,%3}, [%4];"
                 : "=r"(r[0]), "=r"(r[1]), "=r"(r[2]), "=r"(r[3]) : "r"(addr));
}
__device__ __forceinline__ void mma16816(float* d, const uint32_t* a, uint32_t b0, uint32_t b1) {
    asm volatile(
        "mma.sync.aligned.m16n8k16.row.col.f32.bf16.bf16.f32 "
        "{%0,%1,%2,%3}, {%4,%5,%6,%7}, {%8,%9}, {%0,%1,%2,%3};"
        : "+f"(d[0]), "+f"(d[1]), "+f"(d[2]), "+f"(d[3])
        : "r"(a[0]), "r"(a[1]), "r"(a[2]), "r"(a[3]), "r"(b0), "r"(b1));
}
__device__ __forceinline__ void cp16(uint32_t dst, const void* src) {
    asm volatile("cp.async.cg.shared.global [%0], [%1], 16;" :: "r"(dst), "l"(src) : "memory");
}
#define CP_COMMIT() asm volatile("cp.async.commit_group;" ::: "memory")
#define CP_WAIT0()  asm volatile("cp.async.wait_group 0;" ::: "memory")

// ---------------- GEMM + bias: C[M,256] = A[M,768] @ W[768,256] + b ----------------
__global__ void gemm_bias_kernel(const float* __restrict__ A, const float* __restrict__ W,
                                 const float* __restrict__ bias, float* __restrict__ C) {
    __shared__ __align__(16) float Ast[16][64];
    __shared__ __align__(16) float Bs[16][64];
    const int tid = threadIdx.x;
    const int tx = tid & 15, ty = tid >> 4;
    const int m0 = blockIdx.y * 64, n0 = blockIdx.x * 64;
    const int arow = tid & 63, ak4 = (tid >> 6) << 2;
    const int bk = tid >> 4, bn4 = (tid & 15) << 2;
    float acc[4][4] = {};
    for (int k0 = 0; k0 < D_; k0 += 16) {
        float4 av = *reinterpret_cast<const float4*>(A + (size_t)(m0 + arow) * D_ + k0 + ak4);
        Ast[ak4 + 0][arow] = av.x; Ast[ak4 + 1][arow] = av.y;
        Ast[ak4 + 2][arow] = av.z; Ast[ak4 + 3][arow] = av.w;
        *reinterpret_cast<float4*>(&Bs[bk][bn4]) =
            *reinterpret_cast<const float4*>(W + (size_t)(k0 + bk) * E_ + n0 + bn4);
        __syncthreads();
#pragma unroll
        for (int kk = 0; kk < 16; kk++) {
            float4 a4 = *reinterpret_cast<const float4*>(&Ast[kk][ty * 4]);
            float4 b4 = *reinterpret_cast<const float4*>(&Bs[kk][tx * 4]);
            float af[4] = {a4.x, a4.y, a4.z, a4.w};
            float bf[4] = {b4.x, b4.y, b4.z, b4.w};
#pragma unroll
            for (int i = 0; i < 4; i++)
#pragma unroll
                for (int j = 0; j < 4; j++) acc[i][j] += af[i] * bf[j];
        }
        __syncthreads();
    }
#pragma unroll
    for (int i = 0; i < 4; i++) {
        int row = m0 + ty * 4 + i;
#pragma unroll
        for (int j = 0; j < 4; j++) {
            int col = n0 + tx * 4 + j;
            C[(size_t)row * E_ + col] = acc[i][j] + bias[col];
        }
    }
}

// ---------------- l2-normalize rows (f64 norm, f32 division) ----------------
__global__ void norm_rows_kernel(const float* __restrict__ in, float* __restrict__ out, int nrows) {
    int warp = (blockIdx.x * blockDim.x + threadIdx.x) >> 5;
    int lane = threadIdx.x & 31;
    if (warp >= nrows) return;
    const float* r = in + (size_t)warp * E_;
    float v[8]; double s = 0.0;
#pragma unroll
    for (int j = 0; j < 8; j++) { v[j] = r[j * 32 + lane]; s += (double)v[j] * (double)v[j]; }
#pragma unroll
    for (int o = 16; o > 0; o >>= 1) s += __shfl_xor_sync(0xffffffffu, s, o);
    float nf = fmaxf((float)sqrt(s), 1e-12f);
#pragma unroll
    for (int j = 0; j < 8; j++) out[(size_t)warp * E_ + j * 32 + lane] = v[j] / nf;
}

// -------- normalize token rows in-place + f64 dot with per-item global --------
__global__ void norm_tok_sim_kernel(float* __restrict__ tok, const float* __restrict__ glob,
                                    double* __restrict__ sim, int nrows, int tokens_per_item) {
    int warp = (blockIdx.x * blockDim.x + threadIdx.x) >> 5;
    int lane = threadIdx.x & 31;
    if (warp >= nrows) return;
    float* r = tok + (size_t)warp * E_;
    float v[8]; double s = 0.0;
#pragma unroll
    for (int j = 0; j < 8; j++) { v[j] = r[j * 32 + lane]; s += (double)v[j] * (double)v[j]; }
#pragma unroll
    for (int o = 16; o > 0; o >>= 1) s += __shfl_xor_sync(0xffffffffu, s, o);
    float nf = fmaxf((float)sqrt(s), 1e-12f);
    const float* g = glob + (size_t)(warp / tokens_per_item) * E_;
    double d = 0.0;
#pragma unroll
    for (int j = 0; j < 8; j++) {
        float nv = v[j] / nf;
        r[j * 32 + lane] = nv;
        d += (double)nv * (double)g[j * 32 + lane];
    }
#pragma unroll
    for (int o = 16; o > 0; o >>= 1) d += __shfl_xor_sync(0xffffffffu, d, o);
    if (lane == 0) sim[warp] = d;
}

// ---------------- top-K per item, descending, lowest-index tie-break ----------------
__global__ void topk_kernel(const double* __restrict__ sim, int* __restrict__ out, int n) {
    __shared__ double vals[256];
    __shared__ double wv[8];
    __shared__ int wi[8];
    int b = blockIdx.x;
    int t = threadIdx.x;
    vals[t] = (t < n) ? sim[(size_t)b * n + t] : -1e300;
    __syncthreads();
    for (int k = 0; k < K_; k++) {
        double v = vals[t]; int i = t;
#pragma unroll
        for (int o = 16; o > 0; o >>= 1) {
            double ov = __shfl_xor_sync(0xffffffffu, v, o);
            int oi = __shfl_xor_sync(0xffffffffu, i, o);
            if (ov > v || (ov == v && oi < i)) { v = ov; i = oi; }
        }
        if ((t & 31) == 0) { wv[t >> 5] = v; wi[t >> 5] = i; }
        __syncthreads();
        if (t == 0) {
            double bv = wv[0]; int bi = wi[0];
#pragma unroll
            for (int w = 1; w < 8; w++)
                if (wv[w] > bv || (wv[w] == bv && wi[w] < bi)) { bv = wv[w]; bi = wi[w]; }
            out[b * K_ + k] = bi;
            vals[bi] = -1e300;
        }
        __syncthreads();
    }
}

// ---------------- gather selected normalized tokens into output ----------------
__global__ void gather_kernel(const float* __restrict__ tok, const int* __restrict__ idx,
                              float* __restrict__ outp, int tokens_per_item) {
    int bk = blockIdx.x;
    int item = bk / K_;
    int src = idx[bk];
    const float4* s = reinterpret_cast<const float4*>(tok + ((size_t)item * tokens_per_item + src) * E_);
    float4* d = reinterpret_cast<float4*>(outp + (size_t)bk * E_);
    d[threadIdx.x] = s[threadIdx.x];
}

// ---------------- split f32 -> (hi, lo) bf16, pad 50 -> 64 rows per item ----------------
__global__ void split_pad_kernel(const float* __restrict__ src, __nv_bfloat16* __restrict__ hi,
                                 __nv_bfloat16* __restrict__ lo) {
    int idx = blockIdx.x * 256 + threadIdx.x;   // over [384][64][256]
    int c = idx & 255;
    int r = (idx >> 8) & 63;
    int item = idx >> 14;
    float a = 0.f;
    if (r < K_) a = src[((size_t)item * K_ + r) * E_ + c];
    __nv_bfloat16 h = __float2bfloat16(a);
    __nv_bfloat16 l = __float2bfloat16(a - __bfloat162float(h));
    hi[idx] = h; lo[idx] = l;
}

// ================= mma.sync cross-modal sim + fused max/mean =================
// Block: 128x128 tile (2 b-items x 2 q-items), K=256, 3 bf16-split terms.
// 8 warps, each owns 32 rows x 64 cols. K staged in 8 chunks of 32, double-buffered cp.async.
// smem stage layout per stage: Ahi(8K) Alo(8K) Bhi(8K) Blo(8K); mat = 128 rows x 32 cols bf16,
// row pitch 64B, 16B chunks swizzled: chunk' = chunk ^ (row & 3).
#define STG_BYTES 32768
#define MAT_BYTES 8192
#define DPITCH 129

__global__ void __launch_bounds__(256)
cross_sim_mma_kernel(const __nv_bfloat16* __restrict__ Ahi, const __nv_bfloat16* __restrict__ Alo,
                     const __nv_bfloat16* __restrict__ Bhi, const __nv_bfloat16* __restrict__ Blo,
                     float* __restrict__ i2t, float* __restrict__ t2i) {
    extern __shared__ __align__(16) char dyn[];
    __shared__ float rbuf[128][2];
    __shared__ float cbuf[2][128];

    const uint32_t sbase = smem_u32(dyn);
    const int tid = threadIdx.x;
    const int wid = tid >> 5;
    const int lane = tid & 31;
    const int m0 = blockIdx.y * 128;
    const int n0 = blockIdx.x * 128;
    const int warp_m = wid >> 1;       // 0..3 -> 32-row slab
    const int warp_n = wid & 1;        // 0..1 -> 64-col slab

    const __nv_bfloat16* gmat[4] = { Ahi + (size_t)m0 * E_, Alo + (size_t)m0 * E_,
                                     Bhi + (size_t)n0 * E_, Blo + (size_t)n0 * E_ };

    // ---- stage loader: 2048 x 16B per stage, 8 per thread ----
    auto load_stage = [&](int ks, int buf) {
        uint32_t sb = sbase + buf * STG_BYTES;
#pragma unroll
        for (int it = 0; it < 8; it++) {
            int idx = tid + it * 256;
            int mat = idx >> 9;
            int rem = idx & 511;
            int r = rem >> 2, chunk = rem & 3;
            const void* src = gmat[mat] + (size_t)r * E_ + ks * 32 + chunk * 8;
            uint32_t dst = sb + mat * MAT_BYTES + r * 64 + ((chunk ^ (r & 3)) << 4);
            cp16(dst, src);
        }
        CP_COMMIT();
    };

    float acc[2][8][4] = {};

    load_stage(0, 0);

    for (int ks = 0; ks < 8; ks++) {
        CP_WAIT0();
        __syncthreads();
        if (ks + 1 < 8) load_stage(ks + 1, (ks + 1) & 1);

        uint32_t sb = sbase + (ks & 1) * STG_BYTES;
        const int rA = warp_m * 32 + (lane & 15);          // A row this lane addresses
        const int khalf = lane >> 4;                        // 0: k0-7, 1: k8-15
#pragma unroll
        for (int kstep = 0; kstep < 2; kstep++) {
            uint32_t ahi[2][4], alo[2][4], bhi[4][4], blo[4][4];
            int chunk = kstep * 2 + khalf;
#pragma unroll
            for (int mt = 0; mt < 2; mt++) {
                int r = rA + mt * 16;
                uint32_t off = r * 64 + (((chunk) ^ (r & 3)) << 4);
                ldsm_x4(ahi[mt], sb + 0 * MAT_BYTES + off);
                ldsm_x4(alo[mt], sb + 1 * MAT_BYTES + off);
            }
#pragma unroll
            for (int nt = 0; nt < 4; nt++) {
                int r = warp_n * 64 + nt * 16 + (lane & 15);
                uint32_t off = r * 64 + (((chunk) ^ (r & 3)) << 4);
                ldsm_x4(bhi[nt], sb + 2 * MAT_BYTES + off);
                ldsm_x4(blo[nt], sb + 3 * MAT_BYTES + off);
            }
            // term 0: hi*hi, term 1: hi*lo, term 2: lo*hi
#pragma unroll
            for (int mt = 0; mt < 2; mt++)
#pragma unroll
                for (int nt = 0; nt < 4; nt++) {
                    mma16816(acc[mt][nt * 2 + 0], ahi[mt], bhi[nt][0], bhi[nt][2]);
                    mma16816(acc[mt][nt * 2 + 1], ahi[mt], bhi[nt][1], bhi[nt][3]);
                    mma16816(acc[mt][nt * 2 + 0], ahi[mt], blo[nt][0], blo[nt][2]);
                    mma16816(acc[mt][nt * 2 + 1], ahi[mt], blo[nt][1], blo[nt][3]);
                    mma16816(acc[mt][nt * 2 + 0], alo[mt], bhi[nt][0], bhi[nt][2]);
                    mma16816(acc[mt][nt * 2 + 1], alo[mt], bhi[nt][1], bhi[nt][3]);
                }
        }
        __syncthreads();   // stage buffer free for next prefetch round
    }

    // ---- epilogue: accums -> smem D[128][129] -> masked max/mean ----
    float* D = reinterpret_cast<float*>(dyn);
#pragma unroll
    for (int mt = 0; mt < 2; mt++)
#pragma unroll
        for (int nt8 = 0; nt8 < 8; nt8++) {
            int row = warp_m * 32 + mt * 16 + (lane >> 2);
            int col = warp_n * 64 + nt8 * 8 + (lane & 3) * 2;
            D[row * DPITCH + col]           = acc[mt][nt8][0];
            D[row * DPITCH + col + 1]       = acc[mt][nt8][1];
            D[(row + 8) * DPITCH + col]     = acc[mt][nt8][2];
            D[(row + 8) * DPITCH + col + 1] = acc[mt][nt8][3];
        }
    __syncthreads();

    if (tid < 128) {                 // row maxes over valid t cols (i2t)
        int r = tid;
        float rm0 = -1e30f, rm1 = -1e30f;
        for (int c = 0; c < K_; c++) {
            rm0 = fmaxf(rm0, D[r * DPITCH + c]);
            rm1 = fmaxf(rm1, D[r * DPITCH + 64 + c]);
        }
        rbuf[r][0] = rm0; rbuf[r][1] = rm1;
    } else {                         // col maxes over valid v rows (t2i)
        int j = tid - 128;
        float c0 = -1e30f, c1 = -1e30f;
        for (int r = 0; r < K_; r++) {
            c0 = fmaxf(c0, D[r * DPITCH + j]);
            c1 = fmaxf(c1, D[(64 + r) * DPITCH + j]);
        }
        cbuf[0][j] = c0; cbuf[1][j] = c1;
    }
    __syncthreads();
    if (tid < 4) {                   // i2t: mean over v of rowmax
        int bl = tid >> 1, ql = tid & 1;
        float s = 0.f;
        for (int v = 0; v < K_; v++) s += rbuf[bl * 64 + v][ql];
        i2t[(size_t)(blockIdx.y * 2 + bl) * Q_ + (blockIdx.x * 2 + ql)] = s * (1.0f / 50.0f);
    } else if (tid < 8) {            // t2i: mean over t of colmax
        int k = tid - 4;
        int bl = k >> 1, ql = k & 1;
        float s = 0.f;
        for (int t = 0; t < K_; t++) s += cbuf[bl][ql * 64 + t];
        t2i[(size_t)(blockIdx.y * 2 + bl) * Q_ + (blockIdx.x * 2 + ql)] = s * (1.0f / 50.0f);
    }
}

// ---------------- launch ----------------
extern "C" void kernel_launch(void* const* d_in, const int* in_sizes, int n_in,
                              void* d_out, int out_size) {
    const float* visual_cls     = (const float*)d_in[0];
    const float* visual_tokens  = (const float*)d_in[1];
    const float* textual_cls    = (const float*)d_in[2];
    const float* textual_tokens = (const float*)d_in[3];
    const float* Wv     = (const float*)d_in[4];
    const float* bv     = (const float*)d_in[5];
    const float* Wt     = (const float*)d_in[6];
    const float* bt     = (const float*)d_in[7];
    const float* Wv_tok = (const float*)d_in[8];
    const float* bv_tok = (const float*)d_in[9];
    const float* Wt_tok = (const float*)d_in[10];
    const float* bt_tok = (const float*)d_in[11];

    float* out = (float*)d_out;
    float* o_vcls = out;
    float* o_tcls = o_vcls + B_ * E_;
    float* o_vloc = o_tcls + Q_ * E_;
    float* o_tloc = o_vloc + B_ * K_ * E_;
    float* o_i2t  = o_tloc + Q_ * K_ * E_;
    float* o_t2i  = o_i2t + B_ * Q_;

    float *p_vtok, *p_ttok, *p_vglob, *p_tglob;
    double *p_vsim, *p_tsim;
    int *p_iv, *p_it;
    __nv_bfloat16 *p_vhi, *p_vlo, *p_thi, *p_tlo;
    cudaGetSymbolAddress((void**)&p_vtok, g_vtok);
    cudaGetSymbolAddress((void**)&p_ttok, g_ttok);
    cudaGetSymbolAddress((void**)&p_vglob, g_vglob);
    cudaGetSymbolAddress((void**)&p_tglob, g_tglob);
    cudaGetSymbolAddress((void**)&p_vsim, g_vsim);
    cudaGetSymbolAddress((void**)&p_tsim, g_tsim);
    cudaGetSymbolAddress((void**)&p_iv, g_iv);
    cudaGetSymbolAddress((void**)&p_it, g_it);
    cudaGetSymbolAddress((void**)&p_vhi, g_vhi);
    cudaGetSymbolAddress((void**)&p_vlo, g_vlo);
    cudaGetSymbolAddress((void**)&p_thi, g_thi);
    cudaGetSymbolAddress((void**)&p_tlo, g_tlo);

    // projections (fp32 FFMA — keeps top-k ranking noise at the passing R2 level)
    gemm_bias_kernel<<<dim3(E_ / 64, B_ / 64), 256>>>(visual_cls, Wv, bv, o_vcls);
    gemm_bias_kernel<<<dim3(E_ / 64, Q_ / 64), 256>>>(textual_cls, Wt, bt, o_tcls);
    gemm_bias_kernel<<<dim3(E_ / 64, (B_ * V_) / 64), 256>>>(visual_tokens, Wv_tok, bv_tok, p_vtok);
    gemm_bias_kernel<<<dim3(E_ / 64, (Q_ * T_) / 64), 256>>>(textual_tokens, Wt_tok, bt_tok, p_ttok);

    norm_rows_kernel<<<(B_ * 32) / 256, 256>>>(o_vcls, p_vglob, B_);
    norm_rows_kernel<<<(Q_ * 32) / 256, 256>>>(o_tcls, p_tglob, Q_);

    norm_tok_sim_kernel<<<(B_ * V_ * 32) / 256, 256>>>(p_vtok, p_vglob, p_vsim, B_ * V_, V_);
    norm_tok_sim_kernel<<<(Q_ * T_ * 32) / 256, 256>>>(p_ttok, p_tglob, p_tsim, Q_ * T_, T_);

    topk_kernel<<<B_, 256>>>(p_vsim, p_iv, V_);
    topk_kernel<<<Q_, 256>>>(p_tsim, p_it, T_);
    gather_kernel<<<B_ * K_, 64>>>(p_vtok, p_iv, o_vloc, V_);
    gather_kernel<<<Q_ * K_, 64>>>(p_ttok, p_it, o_tloc, T_);

    // bf16 hi/lo split + zero-pad for tensor-core cross sim
    split_pad_kernel<<<(MR * E_) / 256, 256>>>(o_vloc, p_vhi, p_vlo);
    split_pad_kernel<<<(MR * E_) / 256, 256>>>(o_tloc, p_thi, p_tlo);

    // mma.sync fused cross sim + max/mean
    const int DSMEM = 128 * DPITCH * 4;   // 66,048B >= 2 stages (65,536B)
    cudaFuncSetAttribute(cross_sim_mma_kernel, cudaFuncAttributeMaxDynamicSharedMemorySize, DSMEM);
    cross_sim_mma_kernel<<<dim3(Q_ / 2, B_ / 2), 256, DSMEM>>>(
        p_vhi, p_vlo, p_thi, p_tlo, o_i2t, o_t2i);
}

// round 5
// speedup vs baseline: 3.5243x; 1.4941x over previous
#include <cuda_runtime.h>
#include <cuda_fp16.h>
#include <math.h>
#include <stdint.h>

#define B_ 384
#define Q_ 384
#define V_ 197
#define T_ 100
#define D_ 768
#define E_ 256
#define K_ 50
#define KP 64
#define MR (B_ * KP)

// ---------------- scratch (no allocations allowed) ----------------
__device__ float  g_vtok[B_*V_*E_];
__device__ float  g_ttok[Q_*T_*E_];
__device__ float  g_vglob[B_*E_];
__device__ float  g_tglob[Q_*E_];
__device__ double g_vsim[B_*V_];
__device__ double g_tsim[Q_*T_];
__device__ int    g_iv[B_*K_];
__device__ int    g_it[Q_*K_];
// fp16 split operands for projection GEMMs
__device__ __align__(16) __half g_Avh[B_*V_*D_];
__device__ __align__(16) __half g_Avl[B_*V_*D_];
__device__ __align__(16) __half g_Ath[Q_*T_*D_];
__device__ __align__(16) __half g_Atl[Q_*T_*D_];
__device__ __align__(16) __half g_Acvh[B_*D_];
__device__ __align__(16) __half g_Acvl[B_*D_];
__device__ __align__(16) __half g_Acth[Q_*D_];
__device__ __align__(16) __half g_Actl[Q_*D_];
__device__ __align__(16) __half g_Wvh[E_*D_];
__device__ __align__(16) __half g_Wvl[E_*D_];
__device__ __align__(16) __half g_Wth[E_*D_];
__device__ __align__(16) __half g_Wtl[E_*D_];
__device__ __align__(16) __half g_Wvth[E_*D_];
__device__ __align__(16) __half g_Wvtl[E_*D_];
__device__ __align__(16) __half g_Wtth[E_*D_];
__device__ __align__(16) __half g_Wttl[E_*D_];
// fp16 split selected tokens for cross sim
__device__ __align__(16) __half g_vhi[MR*E_];
__device__ __align__(16) __half g_vlo[MR*E_];
__device__ __align__(16) __half g_thi[MR*E_];

// ================= PTX helpers (baseline ISA — tcgen05 unavailable at compute_103) ======
__device__ __forceinline__ uint32_t smem_u32(const void* p) {
    uint32_t a;
    asm("{ .reg .u64 t; cvta.to.shared.u64 t, %1; cvt.u32.u64 %0, t; }" : "=r"(a) : "l"(p));
    return a;
}
__device__ __forceinline__ void ldsm_x4(uint32_t* r, uint32_t addr) {
    asm volatile("ldmatrix.sync.aligned.m8n8.x4.shared.b16 {%0,%1,%2,%3}, [%4];"
                 : "=r"(r[0]), "=r"(r[1]), "=r"(r[2]), "=r"(r[3]) : "r"(addr));
}
__device__ __forceinline__ void mma16816(float* d, const uint32_t* a, uint32_t b0, uint32_t b1) {
    asm volatile(
        "mma.sync.aligned.m16n8k16.row.col.f32.f16.f16.f32 "
        "{%0,%1,%2,%3}, {%4,%5,%6,%7}, {%8,%9}, {%0,%1,%2,%3};"
        : "+f"(d[0]), "+f"(d[1]), "+f"(d[2]), "+f"(d[3])
        : "r"(a[0]), "r"(a[1]), "r"(a[2]), "r"(a[3]), "r"(b0), "r"(b1));
}
__device__ __forceinline__ void cp16(uint32_t dst, const void* src) {
    asm volatile("cp.async.cg.shared.global [%0], [%1], 16;" :: "r"(dst), "l"(src) : "memory");
}
#define CP_COMMIT() asm volatile("cp.async.commit_group;" ::: "memory")
#define CP_WAIT0()  asm volatile("cp.async.wait_group 0;" ::: "memory")

// ---------------- split f32 -> fp16 (hi, lo), same layout ----------------
__global__ void split_f16_kernel(const float* __restrict__ src, __half* __restrict__ hi,
                                 __half* __restrict__ lo) {
    int i = blockIdx.x * 256 + threadIdx.x;
    float a = src[i];
    __half h = __float2half(a);
    hi[i] = h;
    lo[i] = __float2half(a - __half2float(h));
}

// ---------------- split + transpose weights: [768,256] f32 -> [256,768] fp16 hi/lo ------
__global__ void split_w_kernel(const float* __restrict__ W, __half* __restrict__ hiT,
                               __half* __restrict__ loT) {
    int k = blockIdx.x;       // 768
    int n = threadIdx.x;      // 256
    float a = W[k * E_ + n];
    __half h = __float2half(a);
    hiT[n * D_ + k] = h;
    loT[n * D_ + k] = __float2half(a - __half2float(h));
}

// ================= projection GEMM on HMMA: C[M,256] = A[M,768]@W + b (3-term fp16) =====
// Block 128x128, K staged 32 (24 stages double-buffered). Layout identical to cross kernel.
#define PSTG 32768
#define PMAT 8192
__global__ void __launch_bounds__(256)
proj_mma_kernel(const __half* __restrict__ Ah, const __half* __restrict__ Al,
                const __half* __restrict__ Wh, const __half* __restrict__ Wl,
                const float* __restrict__ bias, float* __restrict__ C) {
    extern __shared__ __align__(16) char dyn[];
    const uint32_t sbase = smem_u32(dyn);
    const int tid = threadIdx.x, wid = tid >> 5, lane = tid & 31;
    const int m0 = blockIdx.y * 128, n0 = blockIdx.x * 128;
    const int warp_m = wid >> 1, warp_n = wid & 1;
    const __half* gmat[4] = { Ah + (size_t)m0 * D_, Al + (size_t)m0 * D_,
                              Wh + (size_t)n0 * D_, Wl + (size_t)n0 * D_ };
    auto load_stage = [&](int ks, int buf) {
        uint32_t sb = sbase + buf * PSTG;
#pragma unroll
        for (int it = 0; it < 8; it++) {
            int idx = tid + it * 256;
            int mat = idx >> 9, rem = idx & 511;
            int r = rem >> 2, chunk = rem & 3;
            const void* src = gmat[mat] + (size_t)r * D_ + ks * 32 + chunk * 8;
            uint32_t dst = sb + mat * PMAT + r * 64 + ((chunk ^ (r & 3)) << 4);
            cp16(dst, src);
        }
        CP_COMMIT();
    };
    float acc[2][8][4] = {};
    load_stage(0, 0);
    for (int ks = 0; ks < 24; ks++) {
        CP_WAIT0();
        __syncthreads();
        if (ks + 1 < 24) load_stage(ks + 1, (ks + 1) & 1);
        uint32_t sb = sbase + (ks & 1) * PSTG;
        const int rA = warp_m * 32 + (lane & 15);
        const int khalf = lane >> 4;
#pragma unroll
        for (int kstep = 0; kstep < 2; kstep++) {
            uint32_t ah[2][4], al[2][4], wh[4][4], wl[4][4];
            int chunk = kstep * 2 + khalf;
#pragma unroll
            for (int mt = 0; mt < 2; mt++) {
                int r = rA + mt * 16;
                uint32_t off = r * 64 + ((chunk ^ (r & 3)) << 4);
                ldsm_x4(ah[mt], sb + 0 * PMAT + off);
                ldsm_x4(al[mt], sb + 1 * PMAT + off);
            }
#pragma unroll
            for (int nt = 0; nt < 4; nt++) {
                int r = warp_n * 64 + nt * 16 + (lane & 15);
                uint32_t off = r * 64 + ((chunk ^ (r & 3)) << 4);
                ldsm_x4(wh[nt], sb + 2 * PMAT + off);
                ldsm_x4(wl[nt], sb + 3 * PMAT + off);
            }
#pragma unroll
            for (int mt = 0; mt < 2; mt++)
#pragma unroll
                for (int nt = 0; nt < 4; nt++) {
                    mma16816(acc[mt][nt * 2 + 0], ah[mt], wh[nt][0], wh[nt][2]);
                    mma16816(acc[mt][nt * 2 + 1], ah[mt], wh[nt][1], wh[nt][3]);
                    mma16816(acc[mt][nt * 2 + 0], ah[mt], wl[nt][0], wl[nt][2]);
                    mma16816(acc[mt][nt * 2 + 1], ah[mt], wl[nt][1], wl[nt][3]);
                    mma16816(acc[mt][nt * 2 + 0], al[mt], wh[nt][0], wh[nt][2]);
                    mma16816(acc[mt][nt * 2 + 1], al[mt], wh[nt][1], wh[nt][3]);
                }
        }
        __syncthreads();
    }
#pragma unroll
    for (int mt = 0; mt < 2; mt++)
#pragma unroll
        for (int nt8 = 0; nt8 < 8; nt8++) {
            int row = m0 + warp_m * 32 + mt * 16 + (lane >> 2);
            int col = n0 + warp_n * 64 + nt8 * 8 + (lane & 3) * 2;
            C[(size_t)row * E_ + col]           = acc[mt][nt8][0] + bias[col];
            C[(size_t)row * E_ + col + 1]       = acc[mt][nt8][1] + bias[col + 1];
            C[(size_t)(row + 8) * E_ + col]     = acc[mt][nt8][2] + bias[col];
            C[(size_t)(row + 8) * E_ + col + 1] = acc[mt][nt8][3] + bias[col + 1];
        }
}

// ---------------- l2-normalize rows (f64 norm, f32 division) ----------------
__global__ void norm_rows_kernel(const float* __restrict__ in, float* __restrict__ out, int nrows) {
    int warp = (blockIdx.x * blockDim.x + threadIdx.x) >> 5;
    int lane = threadIdx.x & 31;
    if (warp >= nrows) return;
    const float* r = in + (size_t)warp * E_;
    float v[8]; double s = 0.0;
#pragma unroll
    for (int j = 0; j < 8; j++) { v[j] = r[j * 32 + lane]; s += (double)v[j] * (double)v[j]; }
#pragma unroll
    for (int o = 16; o > 0; o >>= 1) s += __shfl_xor_sync(0xffffffffu, s, o);
    float nf = fmaxf((float)sqrt(s), 1e-12f);
#pragma unroll
    for (int j = 0; j < 8; j++) out[(size_t)warp * E_ + j * 32 + lane] = v[j] / nf;
}

// -------- normalize token rows in-place + f64 dot with per-item global --------
__global__ void norm_tok_sim_kernel(float* __restrict__ tok, const float* __restrict__ glob,
                                    double* __restrict__ sim, int nrows, int tokens_per_item) {
    int warp = (blockIdx.x * blockDim.x + threadIdx.x) >> 5;
    int lane = threadIdx.x & 31;
    if (warp >= nrows) return;
    float* r = tok + (size_t)warp * E_;
    float v[8]; double s = 0.0;
#pragma unroll
    for (int j = 0; j < 8; j++) { v[j] = r[j * 32 + lane]; s += (double)v[j] * (double)v[j]; }
#pragma unroll
    for (int o = 16; o > 0; o >>= 1) s += __shfl_xor_sync(0xffffffffu, s, o);
    float nf = fmaxf((float)sqrt(s), 1e-12f);
    const float* g = glob + (size_t)(warp / tokens_per_item) * E_;
    double d = 0.0;
#pragma unroll
    for (int j = 0; j < 8; j++) {
        float nv = v[j] / nf;
        r[j * 32 + lane] = nv;
        d += (double)nv * (double)g[j * 32 + lane];
    }
#pragma unroll
    for (int o = 16; o > 0; o >>= 1) d += __shfl_xor_sync(0xffffffffu, d, o);
    if (lane == 0) sim[warp] = d;
}

// ---------------- top-K per item, descending, lowest-index tie-break ----------------
__global__ void topk_kernel(const double* __restrict__ sim, int* __restrict__ out, int n) {
    __shared__ double vals[256];
    __shared__ double wv[8];
    __shared__ int wi[8];
    int b = blockIdx.x;
    int t = threadIdx.x;
    vals[t] = (t < n) ? sim[(size_t)b * n + t] : -1e300;
    __syncthreads();
    for (int k = 0; k < K_; k++) {
        double v = vals[t]; int i = t;
#pragma unroll
        for (int o = 16; o > 0; o >>= 1) {
            double ov = __shfl_xor_sync(0xffffffffu, v, o);
            int oi = __shfl_xor_sync(0xffffffffu, i, o);
            if (ov > v || (ov == v && oi < i)) { v = ov; i = oi; }
        }
        if ((t & 31) == 0) { wv[t >> 5] = v; wi[t >> 5] = i; }
        __syncthreads();
        if (t == 0) {
            double bv = wv[0]; int bi = wi[0];
#pragma unroll
            for (int w = 1; w < 8; w++)
                if (wv[w] > bv || (wv[w] == bv && wi[w] < bi)) { bv = wv[w]; bi = wi[w]; }
            out[b * K_ + k] = bi;
            vals[bi] = -1e300;
        }
        __syncthreads();
    }
}

// ------- gather selected tokens -> f32 output + fp16 hi(/lo) padded scratch -------
__global__ void gather_split_kernel(const float* __restrict__ tok, const int* __restrict__ idx,
                                    float* __restrict__ outp, __half* __restrict__ hi,
                                    __half* __restrict__ lo, int tokens_per_item) {
    int bk = blockIdx.x;                // item*64 + r
    int item = bk >> 6, r = bk & 63;
    int t = threadIdx.x;                // 64 threads x 4 elems
    size_t po = (size_t)(item * KP + r) * E_ + t * 4;
    if (r < K_) {
        int src = idx[item * K_ + r];
        float4 v = *reinterpret_cast<const float4*>(
            tok + ((size_t)item * tokens_per_item + src) * E_ + t * 4);
        *reinterpret_cast<float4*>(outp + (size_t)(item * K_ + r) * E_ + t * 4) = v;
        __half h[4], l[4];
        h[0] = __float2half(v.x); l[0] = __float2half(v.x - __half2float(h[0]));
        h[1] = __float2half(v.y); l[1] = __float2half(v.y - __half2float(h[1]));
        h[2] = __float2half(v.z); l[2] = __float2half(v.z - __half2float(h[2]));
        h[3] = __float2half(v.w); l[3] = __float2half(v.w - __half2float(h[3]));
        *reinterpret_cast<uint2*>(hi + po) = *reinterpret_cast<uint2*>(h);
        if (lo) *reinterpret_cast<uint2*>(lo + po) = *reinterpret_cast<uint2*>(l);
    } else {
        uint2 z = {0u, 0u};
        *reinterpret_cast<uint2*>(hi + po) = z;
        if (lo) *reinterpret_cast<uint2*>(lo + po) = z;
    }
}

// ================= mma.sync cross-modal sim + fused max/mean (2-term fp16) =============
// Block 128x128 tile, K=256 in 8 stages of 32. Terms: Ahi*Bhi + Alo*Bhi (err = <A, B_lo>).
#define STG_BYTES 24576
#define MAT_BYTES 8192
#define DPITCH 129

__global__ void __launch_bounds__(256)
cross_sim_mma_kernel(const __half* __restrict__ Ahi, const __half* __restrict__ Alo,
                     const __half* __restrict__ Bhi,
                     float* __restrict__ i2t, float* __restrict__ t2i) {
    extern __shared__ __align__(16) char dyn[];
    __shared__ float rbuf[128][2];
    __shared__ float cbuf[2][128];

    const uint32_t sbase = smem_u32(dyn);
    const int tid = threadIdx.x;
    const int wid = tid >> 5;
    const int lane = tid & 31;
    const int m0 = blockIdx.y * 128;
    const int n0 = blockIdx.x * 128;
    const int warp_m = wid >> 1;
    const int warp_n = wid & 1;

    const __half* gmat[3] = { Ahi + (size_t)m0 * E_, Alo + (size_t)m0 * E_,
                              Bhi + (size_t)n0 * E_ };

    auto load_stage = [&](int ks, int buf) {
        uint32_t sb = sbase + buf * STG_BYTES;
#pragma unroll
        for (int it = 0; it < 6; it++) {
            int idx = tid + it * 256;
            int mat = idx >> 9, rem = idx & 511;
            int r = rem >> 2, chunk = rem & 3;
            const void* src = gmat[mat] + (size_t)r * E_ + ks * 32 + chunk * 8;
            uint32_t dst = sb + mat * MAT_BYTES + r * 64 + ((chunk ^ (r & 3)) << 4);
            cp16(dst, src);
        }
        CP_COMMIT();
    };

    float acc[2][8][4] = {};
    load_stage(0, 0);

    for (int ks = 0; ks < 8; ks++) {
        CP_WAIT0();
        __syncthreads();
        if (ks + 1 < 8) load_stage(ks + 1, (ks + 1) & 1);

        uint32_t sb = sbase + (ks & 1) * STG_BYTES;
        const int rA = warp_m * 32 + (lane & 15);
        const int khalf = lane >> 4;
#pragma unroll
        for (int kstep = 0; kstep < 2; kstep++) {
            uint32_t ahi[2][4], alo[2][4], bhi[4][4];
            int chunk = kstep * 2 + khalf;
#pragma unroll
            for (int mt = 0; mt < 2; mt++) {
                int r = rA + mt * 16;
                uint32_t off = r * 64 + ((chunk ^ (r & 3)) << 4);
                ldsm_x4(ahi[mt], sb + 0 * MAT_BYTES + off);
                ldsm_x4(alo[mt], sb + 1 * MAT_BYTES + off);
            }
#pragma unroll
            for (int nt = 0; nt < 4; nt++) {
                int r = warp_n * 64 + nt * 16 + (lane & 15);
                uint32_t off = r * 64 + ((chunk ^ (r & 3)) << 4);
                ldsm_x4(bhi[nt], sb + 2 * MAT_BYTES + off);
            }
#pragma unroll
            for (int mt = 0; mt < 2; mt++)
#pragma unroll
                for (int nt = 0; nt < 4; nt++) {
                    mma16816(acc[mt][nt * 2 + 0], ahi[mt], bhi[nt][0], bhi[nt][2]);
                    mma16816(acc[mt][nt * 2 + 1], ahi[mt], bhi[nt][1], bhi[nt][3]);
                    mma16816(acc[mt][nt * 2 + 0], alo[mt], bhi[nt][0], bhi[nt][2]);
                    mma16816(acc[mt][nt * 2 + 1], alo[mt], bhi[nt][1], bhi[nt][3]);
                }
        }
        __syncthreads();
    }

    // ---- epilogue: accums -> smem D[128][129] -> masked max/mean ----
    float* D = reinterpret_cast<float*>(dyn);
#pragma unroll
    for (int mt = 0; mt < 2; mt++)
#pragma unroll
        for (int nt8 = 0; nt8 < 8; nt8++) {
            int row = warp_m * 32 + mt * 16 + (lane >> 2);
            int col = warp_n * 64 + nt8 * 8 + (lane & 3) * 2;
            D[row * DPITCH + col]           = acc[mt][nt8][0];
            D[row * DPITCH + col + 1]       = acc[mt][nt8][1];
            D[(row + 8) * DPITCH + col]     = acc[mt][nt8][2];
            D[(row + 8) * DPITCH + col + 1] = acc[mt][nt8][3];
        }
    __syncthreads();

    if (tid < 128) {
        int r = tid;
        float rm0 = -1e30f, rm1 = -1e30f;
        for (int c = 0; c < K_; c++) {
            rm0 = fmaxf(rm0, D[r * DPITCH + c]);
            rm1 = fmaxf(rm1, D[r * DPITCH + 64 + c]);
        }
        rbuf[r][0] = rm0; rbuf[r][1] = rm1;
    } else {
        int j = tid - 128;
        float c0 = -1e30f, c1 = -1e30f;
        for (int r = 0; r < K_; r++) {
            c0 = fmaxf(c0, D[r * DPITCH + j]);
            c1 = fmaxf(c1, D[(64 + r) * DPITCH + j]);
        }
        cbuf[0][j] = c0; cbuf[1][j] = c1;
    }
    __syncthreads();
    if (tid < 4) {
        int bl = tid >> 1, ql = tid & 1;
        float s = 0.f;
        for (int v = 0; v < K_; v++) s += rbuf[bl * 64 + v][ql];
        i2t[(size_t)(blockIdx.y * 2 + bl) * Q_ + (blockIdx.x * 2 + ql)] = s * (1.0f / 50.0f);
    } else if (tid < 8) {
        int k = tid - 4;
        int bl = k >> 1, ql = k & 1;
        float s = 0.f;
        for (int t = 0; t < K_; t++) s += cbuf[bl][ql * 64 + t];
        t2i[(size_t)(blockIdx.y * 2 + bl) * Q_ + (blockIdx.x * 2 + ql)] = s * (1.0f / 50.0f);
    }
}

// ---------------- launch ----------------
extern "C" void kernel_launch(void* const* d_in, const int* in_sizes, int n_in,
                              void* d_out, int out_size) {
    const float* visual_cls     = (const float*)d_in[0];
    const float* visual_tokens  = (const float*)d_in[1];
    const float* textual_cls    = (const float*)d_in[2];
    const float* textual_tokens = (const float*)d_in[3];
    const float* Wv     = (const float*)d_in[4];
    const float* bv     = (const float*)d_in[5];
    const float* Wt     = (const float*)d_in[6];
    const float* bt     = (const float*)d_in[7];
    const float* Wv_tok = (const float*)d_in[8];
    const float* bv_tok = (const float*)d_in[9];
    const float* Wt_tok = (const float*)d_in[10];
    const float* bt_tok = (const float*)d_in[11];

    float* out = (float*)d_out;
    float* o_vcls = out;
    float* o_tcls = o_vcls + B_ * E_;
    float* o_vloc = o_tcls + Q_ * E_;
    float* o_tloc = o_vloc + B_ * K_ * E_;
    float* o_i2t  = o_tloc + Q_ * K_ * E_;
    float* o_t2i  = o_i2t + B_ * Q_;

    float *p_vtok, *p_ttok, *p_vglob, *p_tglob;
    double *p_vsim, *p_tsim;
    int *p_iv, *p_it;
    __half *p_Avh, *p_Avl, *p_Ath, *p_Atl, *p_Acvh, *p_Acvl, *p_Acth, *p_Actl;
    __half *p_Wvh, *p_Wvl, *p_Wth, *p_Wtl, *p_Wvth, *p_Wvtl, *p_Wtth, *p_Wttl;
    __half *p_vhi, *p_vlo, *p_thi;
    cudaGetSymbolAddress((void**)&p_vtok, g_vtok);
    cudaGetSymbolAddress((void**)&p_ttok, g_ttok);
    cudaGetSymbolAddress((void**)&p_vglob, g_vglob);
    cudaGetSymbolAddress((void**)&p_tglob, g_tglob);
    cudaGetSymbolAddress((void**)&p_vsim, g_vsim);
    cudaGetSymbolAddress((void**)&p_tsim, g_tsim);
    cudaGetSymbolAddress((void**)&p_iv, g_iv);
    cudaGetSymbolAddress((void**)&p_it, g_it);
    cudaGetSymbolAddress((void**)&p_Avh, g_Avh);  cudaGetSymbolAddress((void**)&p_Avl, g_Avl);
    cudaGetSymbolAddress((void**)&p_Ath, g_Ath);  cudaGetSymbolAddress((void**)&p_Atl, g_Atl);
    cudaGetSymbolAddress((void**)&p_Acvh, g_Acvh); cudaGetSymbolAddress((void**)&p_Acvl, g_Acvl);
    cudaGetSymbolAddress((void**)&p_Acth, g_Acth); cudaGetSymbolAddress((void**)&p_Actl, g_Actl);
    cudaGetSymbolAddress((void**)&p_Wvh, g_Wvh);  cudaGetSymbolAddress((void**)&p_Wvl, g_Wvl);
    cudaGetSymbolAddress((void**)&p_Wth, g_Wth);  cudaGetSymbolAddress((void**)&p_Wtl, g_Wtl);
    cudaGetSymbolAddress((void**)&p_Wvth, g_Wvth); cudaGetSymbolAddress((void**)&p_Wvtl, g_Wvtl);
    cudaGetSymbolAddress((void**)&p_Wtth, g_Wtth); cudaGetSymbolAddress((void**)&p_Wttl, g_Wttl);
    cudaGetSymbolAddress((void**)&p_vhi, g_vhi);
    cudaGetSymbolAddress((void**)&p_vlo, g_vlo);
    cudaGetSymbolAddress((void**)&p_thi, g_thi);

    // ---- split inputs & weights to fp16 hi/lo ----
    split_f16_kernel<<<(B_ * V_ * D_) / 256, 256>>>(visual_tokens, p_Avh, p_Avl);
    split_f16_kernel<<<(Q_ * T_ * D_) / 256, 256>>>(textual_tokens, p_Ath, p_Atl);
    split_f16_kernel<<<(B_ * D_) / 256, 256>>>(visual_cls, p_Acvh, p_Acvl);
    split_f16_kernel<<<(Q_ * D_) / 256, 256>>>(textual_cls, p_Acth, p_Actl);
    split_w_kernel<<<D_, E_>>>(Wv, p_Wvh, p_Wvl);
    split_w_kernel<<<D_, E_>>>(Wt, p_Wth, p_Wtl);
    split_w_kernel<<<D_, E_>>>(Wv_tok, p_Wvth, p_Wvtl);
    split_w_kernel<<<D_, E_>>>(Wt_tok, p_Wtth, p_Wttl);

    // ---- projections on HMMA (3-term fp16) ----
    cudaFuncSetAttribute(proj_mma_kernel, cudaFuncAttributeMaxDynamicSharedMemorySize, 2 * PSTG);
    proj_mma_kernel<<<dim3(2, B_ / 128), 256, 2 * PSTG>>>(p_Acvh, p_Acvl, p_Wvh, p_Wvl, bv, o_vcls);
    proj_mma_kernel<<<dim3(2, Q_ / 128), 256, 2 * PSTG>>>(p_Acth, p_Actl, p_Wth, p_Wtl, bt, o_tcls);
    proj_mma_kernel<<<dim3(2, (B_ * V_) / 128), 256, 2 * PSTG>>>(p_Avh, p_Avl, p_Wvth, p_Wvtl, bv_tok, p_vtok);
    proj_mma_kernel<<<dim3(2, (Q_ * T_) / 128), 256, 2 * PSTG>>>(p_Ath, p_Atl, p_Wtth, p_Wttl, bt_tok, p_ttok);

    norm_rows_kernel<<<(B_ * 32) / 256, 256>>>(o_vcls, p_vglob, B_);
    norm_rows_kernel<<<(Q_ * 32) / 256, 256>>>(o_tcls, p_tglob, Q_);

    norm_tok_sim_kernel<<<(B_ * V_ * 32) / 256, 256>>>(p_vtok, p_vglob, p_vsim, B_ * V_, V_);
    norm_tok_sim_kernel<<<(Q_ * T_ * 32) / 256, 256>>>(p_ttok, p_tglob, p_tsim, Q_ * T_, T_);

    topk_kernel<<<B_, 256>>>(p_vsim, p_iv, V_);
    topk_kernel<<<Q_, 256>>>(p_tsim, p_it, T_);
    gather_split_kernel<<<B_ * KP, 64>>>(p_vtok, p_iv, o_vloc, p_vhi, p_vlo, V_);
    gather_split_kernel<<<Q_ * KP, 64>>>(p_ttok, p_it, o_tloc, p_thi, nullptr, T_);

    // ---- 2-term fp16 cross sim + fused max/mean ----
    const int DSMEM = 128 * DPITCH * 4;   // 66,048B >= 2 stages (49,152B)
    cudaFuncSetAttribute(cross_sim_mma_kernel, cudaFuncAttributeMaxDynamicSharedMemorySize, DSMEM);
    cross_sim_mma_kernel<<<dim3(Q_ / 2, B_ / 2), 256, DSMEM>>>(
        p_vhi, p_vlo, p_thi, o_i2t, o_t2i);
}

// round 6
// speedup vs baseline: 4.2065x; 1.1935x over previous
#include <cuda_runtime.h>
#include <cuda_fp16.h>
#include <math.h>
#include <stdint.h>

#define B_ 384
#define Q_ 384
#define V_ 197
#define T_ 100
#define D_ 768
#define E_ 256
#define K_ 50
#define KP 64
#define MR (B_ * KP)

// ---------------- scratch (no allocations allowed) ----------------
__device__ float  g_vtok[B_*V_*E_];
__device__ float  g_ttok[Q_*T_*E_];
__device__ float  g_vglob[B_*E_];
__device__ float  g_tglob[Q_*E_];
__device__ double g_vsim[B_*V_];
__device__ double g_tsim[Q_*T_];
__device__ int    g_iv[B_*K_];
__device__ int    g_it[Q_*K_];
// fp16 split operands for projection GEMMs
__device__ __align__(16) __half g_Avh[B_*V_*D_];
__device__ __align__(16) __half g_Avl[B_*V_*D_];
__device__ __align__(16) __half g_Ath[Q_*T_*D_];
__device__ __align__(16) __half g_Atl[Q_*T_*D_];
__device__ __align__(16) __half g_Acvh[B_*D_];
__device__ __align__(16) __half g_Acvl[B_*D_];
__device__ __align__(16) __half g_Acth[Q_*D_];
__device__ __align__(16) __half g_Actl[Q_*D_];
__device__ __align__(16) __half g_Wvh[E_*D_];
__device__ __align__(16) __half g_Wvl[E_*D_];
__device__ __align__(16) __half g_Wth[E_*D_];
__device__ __align__(16) __half g_Wtl[E_*D_];
__device__ __align__(16) __half g_Wvth[E_*D_];
__device__ __align__(16) __half g_Wvtl[E_*D_];
__device__ __align__(16) __half g_Wtth[E_*D_];
__device__ __align__(16) __half g_Wttl[E_*D_];
// fp16 selected tokens for cross sim (hi only — single-term)
__device__ __align__(16) __half g_vhi[MR*E_];
__device__ __align__(16) __half g_thi[MR*E_];

// ================= PTX helpers (baseline ISA — tcgen05 unavailable at compute_103) ======
__device__ __forceinline__ uint32_t smem_u32(const void* p) {
    uint32_t a;
    asm("{ .reg .u64 t; cvta.to.shared.u64 t, %1; cvt.u32.u64 %0, t; }" : "=r"(a) : "l"(p));
    return a;
}
__device__ __forceinline__ void ldsm_x4(uint32_t* r, uint32_t addr) {
    asm volatile("ldmatrix.sync.aligned.m8n8.x4.shared.b16 {%0,%1,%2,%3}, [%4];"
                 : "=r"(r[0]), "=r"(r[1]), "=r"(r[2]), "=r"(r[3]) : "r"(addr));
}
__device__ __forceinline__ void mma16816(float* d, const uint32_t* a, uint32_t b0, uint32_t b1) {
    asm volatile(
        "mma.sync.aligned.m16n8k16.row.col.f32.f16.f16.f32 "
        "{%0,%1,%2,%3}, {%4,%5,%6,%7}, {%8,%9}, {%0,%1,%2,%3};"
        : "+f"(d[0]), "+f"(d[1]), "+f"(d[2]), "+f"(d[3])
        : "r"(a[0]), "r"(a[1]), "r"(a[2]), "r"(a[3]), "r"(b0), "r"(b1));
}
__device__ __forceinline__ void cp16(uint32_t dst, const void* src) {
    asm volatile("cp.async.cg.shared.global [%0], [%1], 16;" :: "r"(dst), "l"(src) : "memory");
}
#define CP_COMMIT() asm volatile("cp.async.commit_group;" ::: "memory")
#define CP_WAIT0()  asm volatile("cp.async.wait_group 0;" ::: "memory")

// ---------------- split f32 -> fp16 (hi, lo), same layout ----------------
__global__ void split_f16_kernel(const float* __restrict__ src, __half* __restrict__ hi,
                                 __half* __restrict__ lo) {
    int i = blockIdx.x * 256 + threadIdx.x;
    float a = src[i];
    __half h = __float2half(a);
    hi[i] = h;
    lo[i] = __float2half(a - __half2float(h));
}

// ---------------- split + transpose weights: [768,256] f32 -> [256,768] fp16 hi/lo ------
__global__ void split_w_kernel(const float* __restrict__ W, __half* __restrict__ hiT,
                               __half* __restrict__ loT) {
    int k = blockIdx.x;       // 768
    int n = threadIdx.x;      // 256
    float a = W[k * E_ + n];
    __half h = __float2half(a);
    hiT[n * D_ + k] = h;
    loT[n * D_ + k] = __float2half(a - __half2float(h));
}

// ================= projection GEMM on HMMA: C[M,256] = A[M,768]@W + b (3-term fp16) =====
#define PSTG 32768
#define PMAT 8192
__global__ void __launch_bounds__(256)
proj_mma_kernel(const __half* __restrict__ Ah, const __half* __restrict__ Al,
                const __half* __restrict__ Wh, const __half* __restrict__ Wl,
                const float* __restrict__ bias, float* __restrict__ C) {
    extern __shared__ __align__(16) char dyn[];
    const uint32_t sbase = smem_u32(dyn);
    const int tid = threadIdx.x, wid = tid >> 5, lane = tid & 31;
    const int m0 = blockIdx.y * 128, n0 = blockIdx.x * 128;
    const int warp_m = wid >> 1, warp_n = wid & 1;
    const __half* gmat[4] = { Ah + (size_t)m0 * D_, Al + (size_t)m0 * D_,
                              Wh + (size_t)n0 * D_, Wl + (size_t)n0 * D_ };
    auto load_stage = [&](int ks, int buf) {
        uint32_t sb = sbase + buf * PSTG;
#pragma unroll
        for (int it = 0; it < 8; it++) {
            int idx = tid + it * 256;
            int mat = idx >> 9, rem = idx & 511;
            int r = rem >> 2, chunk = rem & 3;
            const void* src = gmat[mat] + (size_t)r * D_ + ks * 32 + chunk * 8;
            uint32_t dst = sb + mat * PMAT + r * 64 + ((chunk ^ (r & 3)) << 4);
            cp16(dst, src);
        }
        CP_COMMIT();
    };
    float acc[2][8][4] = {};
    load_stage(0, 0);
    for (int ks = 0; ks < 24; ks++) {
        CP_WAIT0();
        __syncthreads();
        if (ks + 1 < 24) load_stage(ks + 1, (ks + 1) & 1);
        uint32_t sb = sbase + (ks & 1) * PSTG;
        const int rA = warp_m * 32 + (lane & 15);
        const int khalf = lane >> 4;
#pragma unroll
        for (int kstep = 0; kstep < 2; kstep++) {
            uint32_t ah[2][4], al[2][4], wh[4][4], wl[4][4];
            int chunk = kstep * 2 + khalf;
#pragma unroll
            for (int mt = 0; mt < 2; mt++) {
                int r = rA + mt * 16;
                uint32_t off = r * 64 + ((chunk ^ (r & 3)) << 4);
                ldsm_x4(ah[mt], sb + 0 * PMAT + off);
                ldsm_x4(al[mt], sb + 1 * PMAT + off);
            }
#pragma unroll
            for (int nt = 0; nt < 4; nt++) {
                int r = warp_n * 64 + nt * 16 + (lane & 15);
                uint32_t off = r * 64 + ((chunk ^ (r & 3)) << 4);
                ldsm_x4(wh[nt], sb + 2 * PMAT + off);
                ldsm_x4(wl[nt], sb + 3 * PMAT + off);
            }
#pragma unroll
            for (int mt = 0; mt < 2; mt++)
#pragma unroll
                for (int nt = 0; nt < 4; nt++) {
                    mma16816(acc[mt][nt * 2 + 0], ah[mt], wh[nt][0], wh[nt][2]);
                    mma16816(acc[mt][nt * 2 + 1], ah[mt], wh[nt][1], wh[nt][3]);
                    mma16816(acc[mt][nt * 2 + 0], ah[mt], wl[nt][0], wl[nt][2]);
                    mma16816(acc[mt][nt * 2 + 1], ah[mt], wl[nt][1], wl[nt][3]);
                    mma16816(acc[mt][nt * 2 + 0], al[mt], wh[nt][0], wh[nt][2]);
                    mma16816(acc[mt][nt * 2 + 1], al[mt], wh[nt][1], wh[nt][3]);
                }
        }
        __syncthreads();
    }
#pragma unroll
    for (int mt = 0; mt < 2; mt++)
#pragma unroll
        for (int nt8 = 0; nt8 < 8; nt8++) {
            int row = m0 + warp_m * 32 + mt * 16 + (lane >> 2);
            int col = n0 + warp_n * 64 + nt8 * 8 + (lane & 3) * 2;
            C[(size_t)row * E_ + col]           = acc[mt][nt8][0] + bias[col];
            C[(size_t)row * E_ + col + 1]       = acc[mt][nt8][1] + bias[col + 1];
            C[(size_t)(row + 8) * E_ + col]     = acc[mt][nt8][2] + bias[col];
            C[(size_t)(row + 8) * E_ + col + 1] = acc[mt][nt8][3] + bias[col + 1];
        }
}

// ---------------- l2-normalize rows (f64 norm, f32 division) ----------------
__global__ void norm_rows_kernel(const float* __restrict__ in, float* __restrict__ out, int nrows) {
    int warp = (blockIdx.x * blockDim.x + threadIdx.x) >> 5;
    int lane = threadIdx.x & 31;
    if (warp >= nrows) return;
    const float* r = in + (size_t)warp * E_;
    float v[8]; double s = 0.0;
#pragma unroll
    for (int j = 0; j < 8; j++) { v[j] = r[j * 32 + lane]; s += (double)v[j] * (double)v[j]; }
#pragma unroll
    for (int o = 16; o > 0; o >>= 1) s += __shfl_xor_sync(0xffffffffu, s, o);
    float nf = fmaxf((float)sqrt(s), 1e-12f);
#pragma unroll
    for (int j = 0; j < 8; j++) out[(size_t)warp * E_ + j * 32 + lane] = v[j] / nf;
}

// -------- normalize token rows in-place + f64 dot with per-item global --------
__global__ void norm_tok_sim_kernel(float* __restrict__ tok, const float* __restrict__ glob,
                                    double* __restrict__ sim, int nrows, int tokens_per_item) {
    int warp = (blockIdx.x * blockDim.x + threadIdx.x) >> 5;
    int lane = threadIdx.x & 31;
    if (warp >= nrows) return;
    float* r = tok + (size_t)warp * E_;
    float v[8]; double s = 0.0;
#pragma unroll
    for (int j = 0; j < 8; j++) { v[j] = r[j * 32 + lane]; s += (double)v[j] * (double)v[j]; }
#pragma unroll
    for (int o = 16; o > 0; o >>= 1) s += __shfl_xor_sync(0xffffffffu, s, o);
    float nf = fmaxf((float)sqrt(s), 1e-12f);
    const float* g = glob + (size_t)(warp / tokens_per_item) * E_;
    double d = 0.0;
#pragma unroll
    for (int j = 0; j < 8; j++) {
        float nv = v[j] / nf;
        r[j * 32 + lane] = nv;
        d += (double)nv * (double)g[j * 32 + lane];
    }
#pragma unroll
    for (int o = 16; o > 0; o >>= 1) d += __shfl_xor_sync(0xffffffffu, d, o);
    if (lane == 0) sim[warp] = d;
}

// ---------------- top-K per item, descending, lowest-index tie-break ----------------
__global__ void topk_kernel(const double* __restrict__ sim, int* __restrict__ out, int n) {
    __shared__ double vals[256];
    __shared__ double wv[8];
    __shared__ int wi[8];
    int b = blockIdx.x;
    int t = threadIdx.x;
    vals[t] = (t < n) ? sim[(size_t)b * n + t] : -1e300;
    __syncthreads();
    for (int k = 0; k < K_; k++) {
        double v = vals[t]; int i = t;
#pragma unroll
        for (int o = 16; o > 0; o >>= 1) {
            double ov = __shfl_xor_sync(0xffffffffu, v, o);
            int oi = __shfl_xor_sync(0xffffffffu, i, o);
            if (ov > v || (ov == v && oi < i)) { v = ov; i = oi; }
        }
        if ((t & 31) == 0) { wv[t >> 5] = v; wi[t >> 5] = i; }
        __syncthreads();
        if (t == 0) {
            double bv = wv[0]; int bi = wi[0];
#pragma unroll
            for (int w = 1; w < 8; w++)
                if (wv[w] > bv || (wv[w] == bv && wi[w] < bi)) { bv = wv[w]; bi = wi[w]; }
            out[b * K_ + k] = bi;
            vals[bi] = -1e300;
        }
        __syncthreads();
    }
}

// ------- gather selected tokens -> f32 output + fp16 hi padded scratch -------
__global__ void gather_split_kernel(const float* __restrict__ tok, const int* __restrict__ idx,
                                    float* __restrict__ outp, __half* __restrict__ hi,
                                    int tokens_per_item) {
    int bk = blockIdx.x;                // item*64 + r
    int item = bk >> 6, r = bk & 63;
    int t = threadIdx.x;                // 64 threads x 4 elems
    size_t po = (size_t)(item * KP + r) * E_ + t * 4;
    if (r < K_) {
        int src = idx[item * K_ + r];
        float4 v = *reinterpret_cast<const float4*>(
            tok + ((size_t)item * tokens_per_item + src) * E_ + t * 4);
        *reinterpret_cast<float4*>(outp + (size_t)(item * K_ + r) * E_ + t * 4) = v;
        __half h[4];
        h[0] = __float2half(v.x); h[1] = __float2half(v.y);
        h[2] = __float2half(v.z); h[3] = __float2half(v.w);
        *reinterpret_cast<uint2*>(hi + po) = *reinterpret_cast<uint2*>(h);
    } else {
        uint2 z = {0u, 0u};
        *reinterpret_cast<uint2*>(hi + po) = z;
    }
}

// ================= mma.sync cross-modal sim + fused max/mean (single-term fp16) ========
// Block 128x128 tile, K=256 in 8 stages of 32. sim ≈ Ahi·Bhi (err = <a,b_lo>+<a_lo,b_hi>).
#define STG_BYTES 16384
#define MAT_BYTES 8192
#define DPITCH 129

__global__ void __launch_bounds__(256)
cross_sim_mma_kernel(const __half* __restrict__ Ahi, const __half* __restrict__ Bhi,
                     float* __restrict__ i2t, float* __restrict__ t2i) {
    extern __shared__ __align__(16) char dyn[];
    __shared__ float rbuf[128][2];
    __shared__ float cbuf[2][128];

    const uint32_t sbase = smem_u32(dyn);
    const int tid = threadIdx.x;
    const int wid = tid >> 5;
    const int lane = tid & 31;
    const int m0 = blockIdx.y * 128;
    const int n0 = blockIdx.x * 128;
    const int warp_m = wid >> 1;
    const int warp_n = wid & 1;

    const __half* gmat[2] = { Ahi + (size_t)m0 * E_, Bhi + (size_t)n0 * E_ };

    auto load_stage = [&](int ks, int buf) {
        uint32_t sb = sbase + buf * STG_BYTES;
#pragma unroll
        for (int it = 0; it < 4; it++) {
            int idx = tid + it * 256;
            int mat = idx >> 9, rem = idx & 511;
            int r = rem >> 2, chunk = rem & 3;
            const void* src = gmat[mat] + (size_t)r * E_ + ks * 32 + chunk * 8;
            uint32_t dst = sb + mat * MAT_BYTES + r * 64 + ((chunk ^ (r & 3)) << 4);
            cp16(dst, src);
        }
        CP_COMMIT();
    };

    float acc[2][8][4] = {};
    load_stage(0, 0);

    for (int ks = 0; ks < 8; ks++) {
        CP_WAIT0();
        __syncthreads();
        if (ks + 1 < 8) load_stage(ks + 1, (ks + 1) & 1);

        uint32_t sb = sbase + (ks & 1) * STG_BYTES;
        const int rA = warp_m * 32 + (lane & 15);
        const int khalf = lane >> 4;
#pragma unroll
        for (int kstep = 0; kstep < 2; kstep++) {
            uint32_t ahi[2][4], bhi[4][4];
            int chunk = kstep * 2 + khalf;
#pragma unroll
            for (int mt = 0; mt < 2; mt++) {
                int r = rA + mt * 16;
                uint32_t off = r * 64 + ((chunk ^ (r & 3)) << 4);
                ldsm_x4(ahi[mt], sb + 0 * MAT_BYTES + off);
            }
#pragma unroll
            for (int nt = 0; nt < 4; nt++) {
                int r = warp_n * 64 + nt * 16 + (lane & 15);
                uint32_t off = r * 64 + ((chunk ^ (r & 3)) << 4);
                ldsm_x4(bhi[nt], sb + 1 * MAT_BYTES + off);
            }
#pragma unroll
            for (int mt = 0; mt < 2; mt++)
#pragma unroll
                for (int nt = 0; nt < 4; nt++) {
                    mma16816(acc[mt][nt * 2 + 0], ahi[mt], bhi[nt][0], bhi[nt][2]);
                    mma16816(acc[mt][nt * 2 + 1], ahi[mt], bhi[nt][1], bhi[nt][3]);
                }
        }
        __syncthreads();
    }

    // ---- epilogue: accums -> smem D[128][129] -> masked max/mean ----
    float* D = reinterpret_cast<float*>(dyn);
#pragma unroll
    for (int mt = 0; mt < 2; mt++)
#pragma unroll
        for (int nt8 = 0; nt8 < 8; nt8++) {
            int row = warp_m * 32 + mt * 16 + (lane >> 2);
            int col = warp_n * 64 + nt8 * 8 + (lane & 3) * 2;
            D[row * DPITCH + col]           = acc[mt][nt8][0];
            D[row * DPITCH + col + 1]       = acc[mt][nt8][1];
            D[(row + 8) * DPITCH + col]     = acc[mt][nt8][2];
            D[(row + 8) * DPITCH + col + 1] = acc[mt][nt8][3];
        }
    __syncthreads();

    if (tid < 128) {
        int r = tid;
        float rm0 = -1e30f, rm1 = -1e30f;
        for (int c = 0; c < K_; c++) {
            rm0 = fmaxf(rm0, D[r * DPITCH + c]);
            rm1 = fmaxf(rm1, D[r * DPITCH + 64 + c]);
        }
        rbuf[r][0] = rm0; rbuf[r][1] = rm1;
    } else {
        int j = tid - 128;
        float c0 = -1e30f, c1 = -1e30f;
        for (int r = 0; r < K_; r++) {
            c0 = fmaxf(c0, D[r * DPITCH + j]);
            c1 = fmaxf(c1, D[(64 + r) * DPITCH + j]);
        }
        cbuf[0][j] = c0; cbuf[1][j] = c1;
    }
    __syncthreads();
    if (tid < 4) {
        int bl = tid >> 1, ql = tid & 1;
        float s = 0.f;
        for (int v = 0; v < K_; v++) s += rbuf[bl * 64 + v][ql];
        i2t[(size_t)(blockIdx.y * 2 + bl) * Q_ + (blockIdx.x * 2 + ql)] = s * (1.0f / 50.0f);
    } else if (tid < 8) {
        int k = tid - 4;
        int bl = k >> 1, ql = k & 1;
        float s = 0.f;
        for (int t = 0; t < K_; t++) s += cbuf[bl][ql * 64 + t];
        t2i[(size_t)(blockIdx.y * 2 + bl) * Q_ + (blockIdx.x * 2 + ql)] = s * (1.0f / 50.0f);
    }
}

// ---------------- launch ----------------
extern "C" void kernel_launch(void* const* d_in, const int* in_sizes, int n_in,
                              void* d_out, int out_size) {
    const float* visual_cls     = (const float*)d_in[0];
    const float* visual_tokens  = (const float*)d_in[1];
    const float* textual_cls    = (const float*)d_in[2];
    const float* textual_tokens = (const float*)d_in[3];
    const float* Wv     = (const float*)d_in[4];
    const float* bv     = (const float*)d_in[5];
    const float* Wt     = (const float*)d_in[6];
    const float* bt     = (const float*)d_in[7];
    const float* Wv_tok = (const float*)d_in[8];
    const float* bv_tok = (const float*)d_in[9];
    const float* Wt_tok = (const float*)d_in[10];
    const float* bt_tok = (const float*)d_in[11];

    float* out = (float*)d_out;
    float* o_vcls = out;
    float* o_tcls = o_vcls + B_ * E_;
    float* o_vloc = o_tcls + Q_ * E_;
    float* o_tloc = o_vloc + B_ * K_ * E_;
    float* o_i2t  = o_tloc + Q_ * K_ * E_;
    float* o_t2i  = o_i2t + B_ * Q_;

    float *p_vtok, *p_ttok, *p_vglob, *p_tglob;
    double *p_vsim, *p_tsim;
    int *p_iv, *p_it;
    __half *p_Avh, *p_Avl, *p_Ath, *p_Atl, *p_Acvh, *p_Acvl, *p_Acth, *p_Actl;
    __half *p_Wvh, *p_Wvl, *p_Wth, *p_Wtl, *p_Wvth, *p_Wvtl, *p_Wtth, *p_Wttl;
    __half *p_vhi, *p_thi;
    cudaGetSymbolAddress((void**)&p_vtok, g_vtok);
    cudaGetSymbolAddress((void**)&p_ttok, g_ttok);
    cudaGetSymbolAddress((void**)&p_vglob, g_vglob);
    cudaGetSymbolAddress((void**)&p_tglob, g_tglob);
    cudaGetSymbolAddress((void**)&p_vsim, g_vsim);
    cudaGetSymbolAddress((void**)&p_tsim, g_tsim);
    cudaGetSymbolAddress((void**)&p_iv, g_iv);
    cudaGetSymbolAddress((void**)&p_it, g_it);
    cudaGetSymbolAddress((void**)&p_Avh, g_Avh);  cudaGetSymbolAddress((void**)&p_Avl, g_Avl);
    cudaGetSymbolAddress((void**)&p_Ath, g_Ath);  cudaGetSymbolAddress((void**)&p_Atl, g_Atl);
    cudaGetSymbolAddress((void**)&p_Acvh, g_Acvh); cudaGetSymbolAddress((void**)&p_Acvl, g_Acvl);
    cudaGetSymbolAddress((void**)&p_Acth, g_Acth); cudaGetSymbolAddress((void**)&p_Actl, g_Actl);
    cudaGetSymbolAddress((void**)&p_Wvh, g_Wvh);  cudaGetSymbolAddress((void**)&p_Wvl, g_Wvl);
    cudaGetSymbolAddress((void**)&p_Wth, g_Wth);  cudaGetSymbolAddress((void**)&p_Wtl, g_Wtl);
    cudaGetSymbolAddress((void**)&p_Wvth, g_Wvth); cudaGetSymbolAddress((void**)&p_Wvtl, g_Wvtl);
    cudaGetSymbolAddress((void**)&p_Wtth, g_Wtth); cudaGetSymbolAddress((void**)&p_Wttl, g_Wttl);
    cudaGetSymbolAddress((void**)&p_vhi, g_vhi);
    cudaGetSymbolAddress((void**)&p_thi, g_thi);

    // ---- split inputs & weights to fp16 hi/lo ----
    split_f16_kernel<<<(B_ * V_ * D_) / 256, 256>>>(visual_tokens, p_Avh, p_Avl);
    split_f16_kernel<<<(Q_ * T_ * D_) / 256, 256>>>(textual_tokens, p_Ath, p_Atl);
    split_f16_kernel<<<(B_ * D_) / 256, 256>>>(visual_cls, p_Acvh, p_Acvl);
    split_f16_kernel<<<(Q_ * D_) / 256, 256>>>(textual_cls, p_Acth, p_Actl);
    split_w_kernel<<<D_, E_>>>(Wv, p_Wvh, p_Wvl);
    split_w_kernel<<<D_, E_>>>(Wt, p_Wth, p_Wtl);
    split_w_kernel<<<D_, E_>>>(Wv_tok, p_Wvth, p_Wvtl);
    split_w_kernel<<<D_, E_>>>(Wt_tok, p_Wtth, p_Wttl);

    // ---- projections on HMMA (3-term fp16 — protects top-k ranking keys) ----
    cudaFuncSetAttribute(proj_mma_kernel, cudaFuncAttributeMaxDynamicSharedMemorySize, 2 * PSTG);
    proj_mma_kernel<<<dim3(2, B_ / 128), 256, 2 * PSTG>>>(p_Acvh, p_Acvl, p_Wvh, p_Wvl, bv, o_vcls);
    proj_mma_kernel<<<dim3(2, Q_ / 128), 256, 2 * PSTG>>>(p_Acth, p_Actl, p_Wth, p_Wtl, bt, o_tcls);
    proj_mma_kernel<<<dim3(2, (B_ * V_) / 128), 256, 2 * PSTG>>>(p_Avh, p_Avl, p_Wvth, p_Wvtl, bv_tok, p_vtok);
    proj_mma_kernel<<<dim3(2, (Q_ * T_) / 128), 256, 2 * PSTG>>>(p_Ath, p_Atl, p_Wtth, p_Wttl, bt_tok, p_ttok);

    norm_rows_kernel<<<(B_ * 32) / 256, 256>>>(o_vcls, p_vglob, B_);
    norm_rows_kernel<<<(Q_ * 32) / 256, 256>>>(o_tcls, p_tglob, Q_);

    norm_tok_sim_kernel<<<(B_ * V_ * 32) / 256, 256>>>(p_vtok, p_vglob, p_vsim, B_ * V_, V_);
    norm_tok_sim_kernel<<<(Q_ * T_ * 32) / 256, 256>>>(p_ttok, p_tglob, p_tsim, Q_ * T_, T_);

    topk_kernel<<<B_, 256>>>(p_vsim, p_iv, V_);
    topk_kernel<<<Q_, 256>>>(p_tsim, p_it, T_);
    gather_split_kernel<<<B_ * KP, 64>>>(p_vtok, p_iv, o_vloc, p_vhi, V_);
    gather_split_kernel<<<Q_ * KP, 64>>>(p_ttok, p_it, o_tloc, p_thi, T_);

    // ---- single-term fp16 cross sim + fused max/mean ----
    const int DSMEM = 128 * DPITCH * 4;   // 66,048B >= 2 stages (32,768B) and epilogue tile
    cudaFuncSetAttribute(cross_sim_mma_kernel, cudaFuncAttributeMaxDynamicSharedMemorySize, DSMEM);
    cross_sim_mma_kernel<<<dim3(Q_ / 2, B_ / 2), 256, DSMEM>>>(p_vhi, p_thi, o_i2t, o_t2i);
}

// round 7
// speedup vs baseline: 4.7240x; 1.1230x over previous
#include <cuda_runtime.h>
#include <cuda_fp16.h>
#include <math.h>
#include <stdint.h>

#define B_ 384
#define Q_ 384
#define V_ 197
#define T_ 100
#define D_ 768
#define E_ 256
#define K_ 50
#define KP 64
#define MR (B_ * KP)

// ---------------- scratch (no allocations allowed) ----------------
__device__ float  g_vtok[B_*V_*E_];
__device__ float  g_ttok[Q_*T_*E_];
__device__ float  g_vglob[B_*E_];
__device__ float  g_tglob[Q_*E_];
__device__ double g_vsim[B_*V_];
__device__ double g_tsim[Q_*T_];
__device__ float  g_vnf[B_*V_];
__device__ float  g_tnf[Q_*T_];
__device__ int    g_iv[B_*K_];
__device__ int    g_it[Q_*K_];
// fp16 split operands for projection GEMMs
__device__ __align__(16) __half g_Avh[B_*V_*D_];
__device__ __align__(16) __half g_Avl[B_*V_*D_];
__device__ __align__(16) __half g_Ath[Q_*T_*D_];
__device__ __align__(16) __half g_Atl[Q_*T_*D_];
__device__ __align__(16) __half g_Acvh[B_*D_];
__device__ __align__(16) __half g_Acvl[B_*D_];
__device__ __align__(16) __half g_Acth[Q_*D_];
__device__ __align__(16) __half g_Actl[Q_*D_];
__device__ __align__(16) __half g_Wvh[E_*D_];
__device__ __align__(16) __half g_Wvl[E_*D_];
__device__ __align__(16) __half g_Wth[E_*D_];
__device__ __align__(16) __half g_Wtl[E_*D_];
__device__ __align__(16) __half g_Wvth[E_*D_];
__device__ __align__(16) __half g_Wvtl[E_*D_];
__device__ __align__(16) __half g_Wtth[E_*D_];
__device__ __align__(16) __half g_Wttl[E_*D_];
// fp16 selected tokens for cross sim (hi only — single-term)
__device__ __align__(16) __half g_vhi[MR*E_];
__device__ __align__(16) __half g_thi[MR*E_];

// ================= PTX helpers (baseline ISA — tcgen05 unavailable at compute_103) ======
__device__ __forceinline__ uint32_t smem_u32(const void* p) {
    uint32_t a;
    asm("{ .reg .u64 t; cvta.to.shared.u64 t, %1; cvt.u32.u64 %0, t; }" : "=r"(a) : "l"(p));
    return a;
}
__device__ __forceinline__ void ldsm_x4(uint32_t* r, uint32_t addr) {
    asm volatile("ldmatrix.sync.aligned.m8n8.x4.shared.b16 {%0,%1,%2,%3}, [%4];"
                 : "=r"(r[0]), "=r"(r[1]), "=r"(r[2]), "=r"(r[3]) : "r"(addr));
}
__device__ __forceinline__ void mma16816(float* d, const uint32_t* a, uint32_t b0, uint32_t b1) {
    asm volatile(
        "mma.sync.aligned.m16n8k16.row.col.f32.f16.f16.f32 "
        "{%0,%1,%2,%3}, {%4,%5,%6,%7}, {%8,%9}, {%0,%1,%2,%3};"
        : "+f"(d[0]), "+f"(d[1]), "+f"(d[2]), "+f"(d[3])
        : "r"(a[0]), "r"(a[1]), "r"(a[2]), "r"(a[3]), "r"(b0), "r"(b1));
}
__device__ __forceinline__ void cp16(uint32_t dst, const void* src) {
    asm volatile("cp.async.cg.shared.global [%0], [%1], 16;" :: "r"(dst), "l"(src) : "memory");
}
#define CP_COMMIT() asm volatile("cp.async.commit_group;" ::: "memory")
#define CP_WAIT0()  asm volatile("cp.async.wait_group 0;" ::: "memory")

// ---------------- split f32 -> fp16 (hi, lo), same layout ----------------
__global__ void split_f16_kernel(const float* __restrict__ src, __half* __restrict__ hi,
                                 __half* __restrict__ lo) {
    int i = blockIdx.x * 256 + threadIdx.x;
    float a = src[i];
    __half h = __float2half(a);
    hi[i] = h;
    lo[i] = __float2half(a - __half2float(h));
}

// ---------------- split + transpose weights: [768,256] f32 -> [256,768] fp16 hi/lo ------
__global__ void split_w_kernel(const float* __restrict__ W, __half* __restrict__ hiT,
                               __half* __restrict__ loT) {
    int k = blockIdx.x;
    int n = threadIdx.x;
    float a = W[k * E_ + n];
    __half h = __float2half(a);
    hiT[n * D_ + k] = h;
    loT[n * D_ + k] = __float2half(a - __half2float(h));
}

// ================= projection GEMM on HMMA: C[M,256] = A[M,768]@W + b (3-term fp16) =====
#define PSTG 32768
#define PMAT 8192
__global__ void __launch_bounds__(256)
proj_mma_kernel(const __half* __restrict__ Ah, const __half* __restrict__ Al,
                const __half* __restrict__ Wh, const __half* __restrict__ Wl,
                const float* __restrict__ bias, float* __restrict__ C) {
    extern __shared__ __align__(16) char dyn[];
    const uint32_t sbase = smem_u32(dyn);
    const int tid = threadIdx.x, wid = tid >> 5, lane = tid & 31;
    const int m0 = blockIdx.y * 128, n0 = blockIdx.x * 128;
    const int warp_m = wid >> 1, warp_n = wid & 1;
    const __half* gmat[4] = { Ah + (size_t)m0 * D_, Al + (size_t)m0 * D_,
                              Wh + (size_t)n0 * D_, Wl + (size_t)n0 * D_ };
    auto load_stage = [&](int ks, int buf) {
        uint32_t sb = sbase + buf * PSTG;
#pragma unroll
        for (int it = 0; it < 8; it++) {
            int idx = tid + it * 256;
            int mat = idx >> 9, rem = idx & 511;
            int r = rem >> 2, chunk = rem & 3;
            const void* src = gmat[mat] + (size_t)r * D_ + ks * 32 + chunk * 8;
            uint32_t dst = sb + mat * PMAT + r * 64 + ((chunk ^ (r & 3)) << 4);
            cp16(dst, src);
        }
        CP_COMMIT();
    };
    float acc[2][8][4] = {};
    load_stage(0, 0);
    for (int ks = 0; ks < 24; ks++) {
        CP_WAIT0();
        __syncthreads();
        if (ks + 1 < 24) load_stage(ks + 1, (ks + 1) & 1);
        uint32_t sb = sbase + (ks & 1) * PSTG;
        const int rA = warp_m * 32 + (lane & 15);
        const int khalf = lane >> 4;
#pragma unroll
        for (int kstep = 0; kstep < 2; kstep++) {
            uint32_t ah[2][4], al[2][4], wh[4][4], wl[4][4];
            int chunk = kstep * 2 + khalf;
#pragma unroll
            for (int mt = 0; mt < 2; mt++) {
                int r = rA + mt * 16;
                uint32_t off = r * 64 + ((chunk ^ (r & 3)) << 4);
                ldsm_x4(ah[mt], sb + 0 * PMAT + off);
                ldsm_x4(al[mt], sb + 1 * PMAT + off);
            }
#pragma unroll
            for (int nt = 0; nt < 4; nt++) {
                int r = warp_n * 64 + nt * 16 + (lane & 15);
                uint32_t off = r * 64 + ((chunk ^ (r & 3)) << 4);
                ldsm_x4(wh[nt], sb + 2 * PMAT + off);
                ldsm_x4(wl[nt], sb + 3 * PMAT + off);
            }
#pragma unroll
            for (int mt = 0; mt < 2; mt++)
#pragma unroll
                for (int nt = 0; nt < 4; nt++) {
                    mma16816(acc[mt][nt * 2 + 0], ah[mt], wh[nt][0], wh[nt][2]);
                    mma16816(acc[mt][nt * 2 + 1], ah[mt], wh[nt][1], wh[nt][3]);
                    mma16816(acc[mt][nt * 2 + 0], ah[mt], wl[nt][0], wl[nt][2]);
                    mma16816(acc[mt][nt * 2 + 1], ah[mt], wl[nt][1], wl[nt][3]);
                    mma16816(acc[mt][nt * 2 + 0], al[mt], wh[nt][0], wh[nt][2]);
                    mma16816(acc[mt][nt * 2 + 1], al[mt], wh[nt][1], wh[nt][3]);
                }
        }
        __syncthreads();
    }
#pragma unroll
    for (int mt = 0; mt < 2; mt++)
#pragma unroll
        for (int nt8 = 0; nt8 < 8; nt8++) {
            int row = m0 + warp_m * 32 + mt * 16 + (lane >> 2);
            int col = n0 + warp_n * 64 + nt8 * 8 + (lane & 3) * 2;
            C[(size_t)row * E_ + col]           = acc[mt][nt8][0] + bias[col];
            C[(size_t)row * E_ + col + 1]       = acc[mt][nt8][1] + bias[col + 1];
            C[(size_t)(row + 8) * E_ + col]     = acc[mt][nt8][2] + bias[col];
            C[(size_t)(row + 8) * E_ + col + 1] = acc[mt][nt8][3] + bias[col + 1];
        }
}

// ---------------- l2-normalize rows (f64 norm, f32 division) ----------------
__global__ void norm_rows_kernel(const float* __restrict__ in, float* __restrict__ out, int nrows) {
    int warp = (blockIdx.x * blockDim.x + threadIdx.x) >> 5;
    int lane = threadIdx.x & 31;
    if (warp >= nrows) return;
    const float* r = in + (size_t)warp * E_;
    float v[8]; double s = 0.0;
#pragma unroll
    for (int j = 0; j < 8; j++) { v[j] = r[j * 32 + lane]; s += (double)v[j] * (double)v[j]; }
#pragma unroll
    for (int o = 16; o > 0; o >>= 1) s += __shfl_xor_sync(0xffffffffu, s, o);
    float nf = fmaxf((float)sqrt(s), 1e-12f);
#pragma unroll
    for (int j = 0; j < 8; j++) out[(size_t)warp * E_ + j * 32 + lane] = v[j] / nf;
}

// -------- per-row norm (f64) + f64 dot-with-global sim; norms stored, tok untouched -----
__global__ void tok_sim_kernel(const float* __restrict__ tok, const float* __restrict__ glob,
                               double* __restrict__ sim, float* __restrict__ nfa,
                               int nrows, int tokens_per_item) {
    int warp = (blockIdx.x * blockDim.x + threadIdx.x) >> 5;
    int lane = threadIdx.x & 31;
    if (warp >= nrows) return;
    const float* r = tok + (size_t)warp * E_;
    float v[8]; double s = 0.0;
#pragma unroll
    for (int j = 0; j < 8; j++) { v[j] = r[j * 32 + lane]; s += (double)v[j] * (double)v[j]; }
#pragma unroll
    for (int o = 16; o > 0; o >>= 1) s += __shfl_xor_sync(0xffffffffu, s, o);
    float nf = fmaxf((float)sqrt(s), 1e-12f);
    const float* g = glob + (size_t)(warp / tokens_per_item) * E_;
    double d = 0.0;
#pragma unroll
    for (int j = 0; j < 8; j++) {
        float nv = v[j] / nf;                       // same rounding as before
        d += (double)nv * (double)g[j * 32 + lane]; // exact ranking key
    }
#pragma unroll
    for (int o = 16; o > 0; o >>= 1) d += __shfl_xor_sync(0xffffffffu, d, o);
    if (lane == 0) { sim[warp] = d; nfa[warp] = nf; }
}

// ---------------- top-K per item, descending, lowest-index tie-break ----------------
__global__ void topk_kernel(const double* __restrict__ sim, int* __restrict__ out, int n) {
    __shared__ double vals[256];
    __shared__ double wv[8];
    __shared__ int wi[8];
    int b = blockIdx.x;
    int t = threadIdx.x;
    vals[t] = (t < n) ? sim[(size_t)b * n + t] : -1e300;
    __syncthreads();
    for (int k = 0; k < K_; k++) {
        double v = vals[t]; int i = t;
#pragma unroll
        for (int o = 16; o > 0; o >>= 1) {
            double ov = __shfl_xor_sync(0xffffffffu, v, o);
            int oi = __shfl_xor_sync(0xffffffffu, i, o);
            if (ov > v || (ov == v && oi < i)) { v = ov; i = oi; }
        }
        if ((t & 31) == 0) { wv[t >> 5] = v; wi[t >> 5] = i; }
        __syncthreads();
        if (t == 0) {
            double bv = wv[0]; int bi = wi[0];
#pragma unroll
            for (int w = 1; w < 8; w++)
                if (wv[w] > bv || (wv[w] == bv && wi[w] < bi)) { bv = wv[w]; bi = wi[w]; }
            out[b * K_ + k] = bi;
            vals[bi] = -1e300;
        }
        __syncthreads();
    }
}

// --- gather selected raw tokens, normalize on the fly -> f32 output + fp16 hi scratch ---
__global__ void gather_split_kernel(const float* __restrict__ tok, const float* __restrict__ nfa,
                                    const int* __restrict__ idx, float* __restrict__ outp,
                                    __half* __restrict__ hi, int tokens_per_item) {
    int bk = blockIdx.x;                // item*64 + r
    int item = bk >> 6, r = bk & 63;
    int t = threadIdx.x;                // 64 threads x 4 elems
    size_t po = (size_t)(item * KP + r) * E_ + t * 4;
    if (r < K_) {
        int src = idx[item * K_ + r];
        size_t srow = ((size_t)item * tokens_per_item + src) * E_;
        float nf = nfa[item * tokens_per_item + src];
        float4 v = *reinterpret_cast<const float4*>(tok + srow + t * 4);
        v.x /= nf; v.y /= nf; v.z /= nf; v.w /= nf;   // bit-identical to prior pipeline
        *reinterpret_cast<float4*>(outp + (size_t)(item * K_ + r) * E_ + t * 4) = v;
        __half h[4];
        h[0] = __float2half(v.x); h[1] = __float2half(v.y);
        h[2] = __float2half(v.z); h[3] = __float2half(v.w);
        *reinterpret_cast<uint2*>(hi + po) = *reinterpret_cast<uint2*>(h);
    } else {
        uint2 z = {0u, 0u};
        *reinterpret_cast<uint2*>(hi + po) = z;
    }
}

// ===== mma.sync cross-modal sim, single-term fp16, register epilogue + pad skip =====
#define STG_BYTES 16384
#define MAT_BYTES 8192

__global__ void __launch_bounds__(256)
cross_sim_mma_kernel(const __half* __restrict__ Ahi, const __half* __restrict__ Bhi,
                     float* __restrict__ i2t, float* __restrict__ t2i) {
    extern __shared__ __align__(16) char dyn[];
    __shared__ float rbuf[128][2];
    __shared__ float cpart[4][128];
    __shared__ float cbuf[2][128];

    const uint32_t sbase = smem_u32(dyn);
    const int tid = threadIdx.x;
    const int wid = tid >> 5;
    const int lane = tid & 31;
    const int m0 = blockIdx.y * 128;
    const int n0 = blockIdx.x * 128;
    const int warp_m = wid >> 1;
    const int warp_n = wid & 1;

    const __half* gmat[2] = { Ahi + (size_t)m0 * E_, Bhi + (size_t)n0 * E_ };

    auto load_stage = [&](int ks, int buf) {
        uint32_t sb = sbase + buf * STG_BYTES;
#pragma unroll
        for (int it = 0; it < 4; it++) {
            int idx = tid + it * 256;
            int mat = idx >> 9, rem = idx & 511;
            int r = rem >> 2, chunk = rem & 3;
            const void* src = gmat[mat] + (size_t)r * E_ + ks * 32 + chunk * 8;
            uint32_t dst = sb + mat * MAT_BYTES + r * 64 + ((chunk ^ (r & 3)) << 4);
            cp16(dst, src);
        }
        CP_COMMIT();
    };

    float acc[2][8][4] = {};
    load_stage(0, 0);

    for (int ks = 0; ks < 8; ks++) {
        CP_WAIT0();
        __syncthreads();
        if (ks + 1 < 8) load_stage(ks + 1, (ks + 1) & 1);

        uint32_t sb = sbase + (ks & 1) * STG_BYTES;
        const int rA = warp_m * 32 + (lane & 15);
        const int khalf = lane >> 4;
#pragma unroll
        for (int kstep = 0; kstep < 2; kstep++) {
            uint32_t ahi[2][4], bhi[4][4];
            int chunk = kstep * 2 + khalf;
#pragma unroll
            for (int mt = 0; mt < 2; mt++) {
                int r = rA + mt * 16;
                uint32_t off = r * 64 + ((chunk ^ (r & 3)) << 4);
                ldsm_x4(ahi[mt], sb + 0 * MAT_BYTES + off);
            }
#pragma unroll
            for (int nt = 0; nt < 4; nt++) {
                int r = warp_n * 64 + nt * 16 + (lane & 15);
                uint32_t off = r * 64 + ((chunk ^ (r & 3)) << 4);
                ldsm_x4(bhi[nt], sb + 1 * MAT_BYTES + off);
            }
            // pad-skip: in-item cols 56-63 (n8 tile index 7 = acc[*][7]) are always padding
#pragma unroll
            for (int mt = 0; mt < 2; mt++)
#pragma unroll
                for (int nt = 0; nt < 4; nt++) {
                    mma16816(acc[mt][nt * 2 + 0], ahi[mt], bhi[nt][0], bhi[nt][2]);
                    if (nt < 3)
                        mma16816(acc[mt][nt * 2 + 1], ahi[mt], bhi[nt][1], bhi[nt][3]);
                }
        }
        __syncthreads();
    }

    // ---- register epilogue: masked row/col maxes via shuffles ----
    const int l4 = lane & 3, l8 = lane >> 2;
    // rowmax (max over valid t-cols of this warp's q-item) -> rbuf[row][warp_n]
#pragma unroll
    for (int mt = 0; mt < 2; mt++)
#pragma unroll
        for (int ih = 0; ih < 2; ih++) {
            float rm = -1e30f;
#pragma unroll
            for (int nt8 = 0; nt8 < 7; nt8++)
#pragma unroll
                for (int j = 0; j < 2; j++) {
                    int ci = nt8 * 8 + l4 * 2 + j;
                    if (ci < K_) rm = fmaxf(rm, acc[mt][nt8][ih * 2 + j]);
                }
            rm = fmaxf(rm, __shfl_xor_sync(0xffffffffu, rm, 1));
            rm = fmaxf(rm, __shfl_xor_sync(0xffffffffu, rm, 2));
            if (l4 == 0) rbuf[warp_m * 32 + mt * 16 + l8 + ih * 8][warp_n] = rm;
        }
    // colmax (max over this warp's 32 rows, masked by in-item row validity) -> cpart
#pragma unroll
    for (int nt8 = 0; nt8 < 7; nt8++)
#pragma unroll
        for (int j = 0; j < 2; j++) {
            float cm = -1e30f;
#pragma unroll
            for (int mt = 0; mt < 2; mt++)
#pragma unroll
                for (int ih = 0; ih < 2; ih++) {
                    int rin = (warp_m & 1) * 32 + mt * 16 + l8 + ih * 8;
                    if (rin < K_) cm = fmaxf(cm, acc[mt][nt8][ih * 2 + j]);
                }
            cm = fmaxf(cm, __shfl_xor_sync(0xffffffffu, cm, 4));
            cm = fmaxf(cm, __shfl_xor_sync(0xffffffffu, cm, 8));
            cm = fmaxf(cm, __shfl_xor_sync(0xffffffffu, cm, 16));
            if (l8 == 0) cpart[warp_m][warp_n * 64 + nt8 * 8 + l4 * 2 + j] = cm;
        }
    __syncthreads();

    if (tid >= 128) {                // combine warp_m pairs per b-item
        int j = tid - 128;
        if ((j & 63) < K_) {
            cbuf[0][j] = fmaxf(cpart[0][j], cpart[1][j]);
            cbuf[1][j] = fmaxf(cpart[2][j], cpart[3][j]);
        }
    }
    __syncthreads();
    if (tid < 4) {                   // i2t: mean over v of rowmax
        int bl = tid >> 1, ql = tid & 1;
        float s = 0.f;
        for (int v = 0; v < K_; v++) s += rbuf[bl * 64 + v][ql];
        i2t[(size_t)(blockIdx.y * 2 + bl) * Q_ + (blockIdx.x * 2 + ql)] = s * (1.0f / 50.0f);
    } else if (tid < 8) {            // t2i: mean over t of colmax
        int k = tid - 4;
        int bl = k >> 1, ql = k & 1;
        float s = 0.f;
        for (int t = 0; t < K_; t++) s += cbuf[bl][ql * 64 + t];
        t2i[(size_t)(blockIdx.y * 2 + bl) * Q_ + (blockIdx.x * 2 + ql)] = s * (1.0f / 50.0f);
    }
}

// ---------------- launch ----------------
extern "C" void kernel_launch(void* const* d_in, const int* in_sizes, int n_in,
                              void* d_out, int out_size) {
    const float* visual_cls     = (const float*)d_in[0];
    const float* visual_tokens  = (const float*)d_in[1];
    const float* textual_cls    = (const float*)d_in[2];
    const float* textual_tokens = (const float*)d_in[3];
    const float* Wv     = (const float*)d_in[4];
    const float* bv     = (const float*)d_in[5];
    const float* Wt     = (const float*)d_in[6];
    const float* bt     = (const float*)d_in[7];
    const float* Wv_tok = (const float*)d_in[8];
    const float* bv_tok = (const float*)d_in[9];
    const float* Wt_tok = (const float*)d_in[10];
    const float* bt_tok = (const float*)d_in[11];

    float* out = (float*)d_out;
    float* o_vcls = out;
    float* o_tcls = o_vcls + B_ * E_;
    float* o_vloc = o_tcls + Q_ * E_;
    float* o_tloc = o_vloc + B_ * K_ * E_;
    float* o_i2t  = o_tloc + Q_ * K_ * E_;
    float* o_t2i  = o_i2t + B_ * Q_;

    float *p_vtok, *p_ttok, *p_vglob, *p_tglob, *p_vnf, *p_tnf;
    double *p_vsim, *p_tsim;
    int *p_iv, *p_it;
    __half *p_Avh, *p_Avl, *p_Ath, *p_Atl, *p_Acvh, *p_Acvl, *p_Acth, *p_Actl;
    __half *p_Wvh, *p_Wvl, *p_Wth, *p_Wtl, *p_Wvth, *p_Wvtl, *p_Wtth, *p_Wttl;
    __half *p_vhi, *p_thi;
    cudaGetSymbolAddress((void**)&p_vtok, g_vtok);
    cudaGetSymbolAddress((void**)&p_ttok, g_ttok);
    cudaGetSymbolAddress((void**)&p_vglob, g_vglob);
    cudaGetSymbolAddress((void**)&p_tglob, g_tglob);
    cudaGetSymbolAddress((void**)&p_vsim, g_vsim);
    cudaGetSymbolAddress((void**)&p_tsim, g_tsim);
    cudaGetSymbolAddress((void**)&p_vnf, g_vnf);
    cudaGetSymbolAddress((void**)&p_tnf, g_tnf);
    cudaGetSymbolAddress((void**)&p_iv, g_iv);
    cudaGetSymbolAddress((void**)&p_it, g_it);
    cudaGetSymbolAddress((void**)&p_Avh, g_Avh);  cudaGetSymbolAddress((void**)&p_Avl, g_Avl);
    cudaGetSymbolAddress((void**)&p_Ath, g_Ath);  cudaGetSymbolAddress((void**)&p_Atl, g_Atl);
    cudaGetSymbolAddress((void**)&p_Acvh, g_Acvh); cudaGetSymbolAddress((void**)&p_Acvl, g_Acvl);
    cudaGetSymbolAddress((void**)&p_Acth, g_Acth); cudaGetSymbolAddress((void**)&p_Actl, g_Actl);
    cudaGetSymbolAddress((void**)&p_Wvh, g_Wvh);  cudaGetSymbolAddress((void**)&p_Wvl, g_Wvl);
    cudaGetSymbolAddress((void**)&p_Wth, g_Wth);  cudaGetSymbolAddress((void**)&p_Wtl, g_Wtl);
    cudaGetSymbolAddress((void**)&p_Wvth, g_Wvth); cudaGetSymbolAddress((void**)&p_Wvtl, g_Wvtl);
    cudaGetSymbolAddress((void**)&p_Wtth, g_Wtth); cudaGetSymbolAddress((void**)&p_Wttl, g_Wttl);
    cudaGetSymbolAddress((void**)&p_vhi, g_vhi);
    cudaGetSymbolAddress((void**)&p_thi, g_thi);

    // ---- split inputs & weights to fp16 hi/lo ----
    split_f16_kernel<<<(B_ * V_ * D_) / 256, 256>>>(visual_tokens, p_Avh, p_Avl);
    split_f16_kernel<<<(Q_ * T_ * D_) / 256, 256>>>(textual_tokens, p_Ath, p_Atl);
    split_f16_kernel<<<(B_ * D_) / 256, 256>>>(visual_cls, p_Acvh, p_Acvl);
    split_f16_kernel<<<(Q_ * D_) / 256, 256>>>(textual_cls, p_Acth, p_Actl);
    split_w_kernel<<<D_, E_>>>(Wv, p_Wvh, p_Wvl);
    split_w_kernel<<<D_, E_>>>(Wt, p_Wth, p_Wtl);
    split_w_kernel<<<D_, E_>>>(Wv_tok, p_Wvth, p_Wvtl);
    split_w_kernel<<<D_, E_>>>(Wt_tok, p_Wtth, p_Wttl);

    // ---- projections on HMMA (3-term fp16 — protects top-k ranking keys) ----
    cudaFuncSetAttribute(proj_mma_kernel, cudaFuncAttributeMaxDynamicSharedMemorySize, 2 * PSTG);
    proj_mma_kernel<<<dim3(2, B_ / 128), 256, 2 * PSTG>>>(p_Acvh, p_Acvl, p_Wvh, p_Wvl, bv, o_vcls);
    proj_mma_kernel<<<dim3(2, Q_ / 128), 256, 2 * PSTG>>>(p_Acth, p_Actl, p_Wth, p_Wtl, bt, o_tcls);
    proj_mma_kernel<<<dim3(2, (B_ * V_) / 128), 256, 2 * PSTG>>>(p_Avh, p_Avl, p_Wvth, p_Wvtl, bv_tok, p_vtok);
    proj_mma_kernel<<<dim3(2, (Q_ * T_) / 128), 256, 2 * PSTG>>>(p_Ath, p_Atl, p_Wtth, p_Wttl, bt_tok, p_ttok);

    norm_rows_kernel<<<(B_ * 32) / 256, 256>>>(o_vcls, p_vglob, B_);
    norm_rows_kernel<<<(Q_ * 32) / 256, 256>>>(o_tcls, p_tglob, Q_);

    // sims + per-row norms (token buffers stay raw; normalization deferred to gather)
    tok_sim_kernel<<<(B_ * V_ * 32) / 256, 256>>>(p_vtok, p_vglob, p_vsim, p_vnf, B_ * V_, V_);
    tok_sim_kernel<<<(Q_ * T_ * 32) / 256, 256>>>(p_ttok, p_tglob, p_tsim, p_tnf, Q_ * T_, T_);

    topk_kernel<<<B_, 256>>>(p_vsim, p_iv, V_);
    topk_kernel<<<Q_, 256>>>(p_tsim, p_it, T_);
    gather_split_kernel<<<B_ * KP, 64>>>(p_vtok, p_vnf, p_iv, o_vloc, p_vhi, V_);
    gather_split_kernel<<<Q_ * KP, 64>>>(p_ttok, p_tnf, p_it, o_tloc, p_thi, T_);

    // ---- single-term fp16 cross sim, register epilogue ----
    const int DSMEM = 2 * STG_BYTES;   // 32,768B
    cudaFuncSetAttribute(cross_sim_mma_kernel, cudaFuncAttributeMaxDynamicSharedMemorySize, DSMEM);
    cross_sim_mma_kernel<<<dim3(Q_ / 2, B_ / 2), 256, DSMEM>>>(p_vhi, p_thi, o_i2t, o_t2i);
}

// round 8
// speedup vs baseline: 4.8442x; 1.0254x over previous
#include <cuda_runtime.h>
#include <cuda_fp16.h>
#include <math.h>
#include <stdint.h>

#define B_ 384
#define Q_ 384
#define V_ 197
#define T_ 100
#define D_ 768
#define E_ 256
#define K_ 50
#define KP 64
#define MR (B_ * KP)
#define MPACK (B_ * K_)        // 19200 packed v rows
#define NBY (MPACK / 128)      // 150

// ---------------- scratch (no allocations allowed) ----------------
__device__ float  g_vtok[B_*V_*E_];
__device__ float  g_ttok[Q_*T_*E_];
__device__ float  g_vglob[B_*E_];
__device__ float  g_tglob[Q_*E_];
__device__ double g_vsim[B_*V_];
__device__ double g_tsim[Q_*T_];
__device__ float  g_vnf[B_*V_];
__device__ float  g_tnf[Q_*T_];
__device__ int    g_iv[B_*K_];
__device__ int    g_it[Q_*K_];
// partial reductions for M-packed cross sim
__device__ float  g_pI[NBY*4*Q_];
__device__ float  g_pC[(size_t)NBY*4*Q_*K_];
// fp16 split operands for projection GEMMs
__device__ __align__(16) __half g_Avh[B_*V_*D_];
__device__ __align__(16) __half g_Avl[B_*V_*D_];
__device__ __align__(16) __half g_Ath[Q_*T_*D_];
__device__ __align__(16) __half g_Atl[Q_*T_*D_];
__device__ __align__(16) __half g_Acvh[B_*D_];
__device__ __align__(16) __half g_Acvl[B_*D_];
__device__ __align__(16) __half g_Acth[Q_*D_];
__device__ __align__(16) __half g_Actl[Q_*D_];
__device__ __align__(16) __half g_Wvh[E_*D_];
__device__ __align__(16) __half g_Wvl[E_*D_];
__device__ __align__(16) __half g_Wth[E_*D_];
__device__ __align__(16) __half g_Wtl[E_*D_];
__device__ __align__(16) __half g_Wvth[E_*D_];
__device__ __align__(16) __half g_Wvtl[E_*D_];
__device__ __align__(16) __half g_Wtth[E_*D_];
__device__ __align__(16) __half g_Wttl[E_*D_];
// fp16 selected tokens for cross sim (v packed, t padded)
__device__ __align__(16) __half g_vhi[MR*E_];
__device__ __align__(16) __half g_thi[MR*E_];

// ================= PTX helpers =================
__device__ __forceinline__ uint32_t smem_u32(const void* p) {
    uint32_t a;
    asm("{ .reg .u64 t; cvta.to.shared.u64 t, %1; cvt.u32.u64 %0, t; }" : "=r"(a) : "l"(p));
    return a;
}
__device__ __forceinline__ void ldsm_x4(uint32_t* r, uint32_t addr) {
    asm volatile("ldmatrix.sync.aligned.m8n8.x4.shared.b16 {%0,%1,%2,%3}, [%4];"
                 : "=r"(r[0]), "=r"(r[1]), "=r"(r[2]), "=r"(r[3]) : "r"(addr));
}
__device__ __forceinline__ void mma16816(float* d, const uint32_t* a, uint32_t b0, uint32_t b1) {
    asm volatile(
        "mma.sync.aligned.m16n8k16.row.col.f32.f16.f16.f32 "
        "{%0,%1,%2,%3}, {%4,%5,%6,%7}, {%8,%9}, {%0,%1,%2,%3};"
        : "+f"(d[0]), "+f"(d[1]), "+f"(d[2]), "+f"(d[3])
        : "r"(a[0]), "r"(a[1]), "r"(a[2]), "r"(a[3]), "r"(b0), "r"(b1));
}
__device__ __forceinline__ void cp16(uint32_t dst, const void* src) {
    asm volatile("cp.async.cg.shared.global [%0], [%1], 16;" :: "r"(dst), "l"(src) : "memory");
}
#define CP_COMMIT() asm volatile("cp.async.commit_group;" ::: "memory")
#define CP_WAIT0()  asm volatile("cp.async.wait_group 0;" ::: "memory")

// ---------------- split f32 -> fp16 (hi, lo) ----------------
__global__ void split_f16_kernel(const float* __restrict__ src, __half* __restrict__ hi,
                                 __half* __restrict__ lo) {
    int i = blockIdx.x * 256 + threadIdx.x;
    float a = src[i];
    __half h = __float2half(a);
    hi[i] = h;
    lo[i] = __float2half(a - __half2float(h));
}

// ---------------- split + transpose weights ----------------
__global__ void split_w_kernel(const float* __restrict__ W, __half* __restrict__ hiT,
                               __half* __restrict__ loT) {
    int k = blockIdx.x;
    int n = threadIdx.x;
    float a = W[k * E_ + n];
    __half h = __float2half(a);
    hiT[n * D_ + k] = h;
    loT[n * D_ + k] = __float2half(a - __half2float(h));
}

// ================= projection GEMM on HMMA (3-term fp16) =================
#define PSTG 32768
#define PMAT 8192
__global__ void __launch_bounds__(256)
proj_mma_kernel(const __half* __restrict__ Ah, const __half* __restrict__ Al,
                const __half* __restrict__ Wh, const __half* __restrict__ Wl,
                const float* __restrict__ bias, float* __restrict__ C) {
    extern __shared__ __align__(16) char dyn[];
    const uint32_t sbase = smem_u32(dyn);
    const int tid = threadIdx.x, wid = tid >> 5, lane = tid & 31;
    const int m0 = blockIdx.y * 128, n0 = blockIdx.x * 128;
    const int warp_m = wid >> 1, warp_n = wid & 1;
    const __half* gmat[4] = { Ah + (size_t)m0 * D_, Al + (size_t)m0 * D_,
                              Wh + (size_t)n0 * D_, Wl + (size_t)n0 * D_ };
    auto load_stage = [&](int ks, int buf) {
        uint32_t sb = sbase + buf * PSTG;
#pragma unroll
        for (int it = 0; it < 8; it++) {
            int idx = tid + it * 256;
            int mat = idx >> 9, rem = idx & 511;
            int r = rem >> 2, chunk = rem & 3;
            const void* src = gmat[mat] + (size_t)r * D_ + ks * 32 + chunk * 8;
            uint32_t dst = sb + mat * PMAT + r * 64 + ((chunk ^ (r & 3)) << 4);
            cp16(dst, src);
        }
        CP_COMMIT();
    };
    float acc[2][8][4] = {};
    load_stage(0, 0);
    for (int ks = 0; ks < 24; ks++) {
        CP_WAIT0();
        __syncthreads();
        if (ks + 1 < 24) load_stage(ks + 1, (ks + 1) & 1);
        uint32_t sb = sbase + (ks & 1) * PSTG;
        const int rA = warp_m * 32 + (lane & 15);
        const int khalf = lane >> 4;
#pragma unroll
        for (int kstep = 0; kstep < 2; kstep++) {
            uint32_t ah[2][4], al[2][4], wh[4][4], wl[4][4];
            int chunk = kstep * 2 + khalf;
#pragma unroll
            for (int mt = 0; mt < 2; mt++) {
                int r = rA + mt * 16;
                uint32_t off = r * 64 + ((chunk ^ (r & 3)) << 4);
                ldsm_x4(ah[mt], sb + 0 * PMAT + off);
                ldsm_x4(al[mt], sb + 1 * PMAT + off);
            }
#pragma unroll
            for (int nt = 0; nt < 4; nt++) {
                int r = warp_n * 64 + nt * 16 + (lane & 15);
                uint32_t off = r * 64 + ((chunk ^ (r & 3)) << 4);
                ldsm_x4(wh[nt], sb + 2 * PMAT + off);
                ldsm_x4(wl[nt], sb + 3 * PMAT + off);
            }
#pragma unroll
            for (int mt = 0; mt < 2; mt++)
#pragma unroll
                for (int nt = 0; nt < 4; nt++) {
                    mma16816(acc[mt][nt * 2 + 0], ah[mt], wh[nt][0], wh[nt][2]);
                    mma16816(acc[mt][nt * 2 + 1], ah[mt], wh[nt][1], wh[nt][3]);
                    mma16816(acc[mt][nt * 2 + 0], ah[mt], wl[nt][0], wl[nt][2]);
                    mma16816(acc[mt][nt * 2 + 1], ah[mt], wl[nt][1], wl[nt][3]);
                    mma16816(acc[mt][nt * 2 + 0], al[mt], wh[nt][0], wh[nt][2]);
                    mma16816(acc[mt][nt * 2 + 1], al[mt], wh[nt][1], wh[nt][3]);
                }
        }
        __syncthreads();
    }
#pragma unroll
    for (int mt = 0; mt < 2; mt++)
#pragma unroll
        for (int nt8 = 0; nt8 < 8; nt8++) {
            int row = m0 + warp_m * 32 + mt * 16 + (lane >> 2);
            int col = n0 + warp_n * 64 + nt8 * 8 + (lane & 3) * 2;
            C[(size_t)row * E_ + col]           = acc[mt][nt8][0] + bias[col];
            C[(size_t)row * E_ + col + 1]       = acc[mt][nt8][1] + bias[col + 1];
            C[(size_t)(row + 8) * E_ + col]     = acc[mt][nt8][2] + bias[col];
            C[(size_t)(row + 8) * E_ + col + 1] = acc[mt][nt8][3] + bias[col + 1];
        }
}

// ---------------- l2-normalize rows (f64 norm, f32 division) ----------------
__global__ void norm_rows_kernel(const float* __restrict__ in, float* __restrict__ out, int nrows) {
    int warp = (blockIdx.x * blockDim.x + threadIdx.x) >> 5;
    int lane = threadIdx.x & 31;
    if (warp >= nrows) return;
    const float* r = in + (size_t)warp * E_;
    float v[8]; double s = 0.0;
#pragma unroll
    for (int j = 0; j < 8; j++) { v[j] = r[j * 32 + lane]; s += (double)v[j] * (double)v[j]; }
#pragma unroll
    for (int o = 16; o > 0; o >>= 1) s += __shfl_xor_sync(0xffffffffu, s, o);
    float nf = fmaxf((float)sqrt(s), 1e-12f);
#pragma unroll
    for (int j = 0; j < 8; j++) out[(size_t)warp * E_ + j * 32 + lane] = v[j] / nf;
}

// -------- per-row norm (f64) + f64 dot-with-global sim --------
__global__ void tok_sim_kernel(const float* __restrict__ tok, const float* __restrict__ glob,
                               double* __restrict__ sim, float* __restrict__ nfa,
                               int nrows, int tokens_per_item) {
    int warp = (blockIdx.x * blockDim.x + threadIdx.x) >> 5;
    int lane = threadIdx.x & 31;
    if (warp >= nrows) return;
    const float* r = tok + (size_t)warp * E_;
    float v[8]; double s = 0.0;
#pragma unroll
    for (int j = 0; j < 8; j++) { v[j] = r[j * 32 + lane]; s += (double)v[j] * (double)v[j]; }
#pragma unroll
    for (int o = 16; o > 0; o >>= 1) s += __shfl_xor_sync(0xffffffffu, s, o);
    float nf = fmaxf((float)sqrt(s), 1e-12f);
    const float* g = glob + (size_t)(warp / tokens_per_item) * E_;
    double d = 0.0;
#pragma unroll
    for (int j = 0; j < 8; j++) {
        float nv = v[j] / nf;
        d += (double)nv * (double)g[j * 32 + lane];
    }
#pragma unroll
    for (int o = 16; o > 0; o >>= 1) d += __shfl_xor_sync(0xffffffffu, d, o);
    if (lane == 0) { sim[warp] = d; nfa[warp] = nf; }
}

// ---------------- top-K per item ----------------
__global__ void topk_kernel(const double* __restrict__ sim, int* __restrict__ out, int n) {
    __shared__ double vals[256];
    __shared__ double wv[8];
    __shared__ int wi[8];
    int b = blockIdx.x;
    int t = threadIdx.x;
    vals[t] = (t < n) ? sim[(size_t)b * n + t] : -1e300;
    __syncthreads();
    for (int k = 0; k < K_; k++) {
        double v = vals[t]; int i = t;
#pragma unroll
        for (int o = 16; o > 0; o >>= 1) {
            double ov = __shfl_xor_sync(0xffffffffu, v, o);
            int oi = __shfl_xor_sync(0xffffffffu, i, o);
            if (ov > v || (ov == v && oi < i)) { v = ov; i = oi; }
        }
        if ((t & 31) == 0) { wv[t >> 5] = v; wi[t >> 5] = i; }
        __syncthreads();
        if (t == 0) {
            double bv = wv[0]; int bi = wi[0];
#pragma unroll
            for (int w = 1; w < 8; w++)
                if (wv[w] > bv || (wv[w] == bv && wi[w] < bi)) { bv = wv[w]; bi = wi[w]; }
            out[b * K_ + k] = bi;
            vals[bi] = -1e300;
        }
        __syncthreads();
    }
}

// --- gather v tokens: normalize on the fly -> f32 output + PACKED fp16 scratch ---
__global__ void gather_v_kernel(const float* __restrict__ tok, const float* __restrict__ nfa,
                                const int* __restrict__ idx, float* __restrict__ outp,
                                __half* __restrict__ hi, int tokens_per_item) {
    int bk = blockIdx.x;                // item*K_ + r  (grid B_*K_)
    int item = bk / K_, r = bk % K_;
    int t = threadIdx.x;
    int src = idx[item * K_ + r];
    size_t srow = ((size_t)item * tokens_per_item + src) * E_;
    float nf = nfa[item * tokens_per_item + src];
    float4 v = *reinterpret_cast<const float4*>(tok + srow + t * 4);
    v.x /= nf; v.y /= nf; v.z /= nf; v.w /= nf;
    *reinterpret_cast<float4*>(outp + (size_t)bk * E_ + t * 4) = v;
    __half h[4];
    h[0] = __float2half(v.x); h[1] = __float2half(v.y);
    h[2] = __float2half(v.z); h[3] = __float2half(v.w);
    *reinterpret_cast<uint2*>(hi + (size_t)bk * E_ + t * 4) = *reinterpret_cast<uint2*>(h);
}

// --- gather t tokens: normalize -> f32 output + PADDED fp16 scratch (64 rows/item) ---
__global__ void gather_t_kernel(const float* __restrict__ tok, const float* __restrict__ nfa,
                                const int* __restrict__ idx, float* __restrict__ outp,
                                __half* __restrict__ hi, int tokens_per_item) {
    int bk = blockIdx.x;                // item*64 + r
    int item = bk >> 6, r = bk & 63;
    int t = threadIdx.x;
    size_t po = (size_t)(item * KP + r) * E_ + t * 4;
    if (r < K_) {
        int src = idx[item * K_ + r];
        size_t srow = ((size_t)item * tokens_per_item + src) * E_;
        float nf = nfa[item * tokens_per_item + src];
        float4 v = *reinterpret_cast<const float4*>(tok + srow + t * 4);
        v.x /= nf; v.y /= nf; v.z /= nf; v.w /= nf;
        *reinterpret_cast<float4*>(outp + (size_t)(item * K_ + r) * E_ + t * 4) = v;
        __half h[4];
        h[0] = __float2half(v.x); h[1] = __float2half(v.y);
        h[2] = __float2half(v.z); h[3] = __float2half(v.w);
        *reinterpret_cast<uint2*>(hi + po) = *reinterpret_cast<uint2*>(h);
    } else {
        uint2 z = {0u, 0u};
        *reinterpret_cast<uint2*>(hi + po) = z;
    }
}

// ===== M-packed mma.sync cross sim: partial rowsum/colmax outputs =====
#define STG_BYTES 16384
#define MAT_BYTES 8192

__global__ void __launch_bounds__(256, 2)
cross_sim_mma_kernel(const __half* __restrict__ Ahi, const __half* __restrict__ Bhi,
                     float* __restrict__ gI, float* __restrict__ gC) {
    extern __shared__ __align__(16) char dyn[];
    __shared__ float rbuf[128][2];
    __shared__ float cpart[4][2][128];
    __shared__ int   blids[4][2];

    const uint32_t sbase = smem_u32(dyn);
    const int tid = threadIdx.x;
    const int wid = tid >> 5;
    const int lane = tid & 31;
    const int by = blockIdx.y;          // 0..149 (packed v rows)
    const int n0 = blockIdx.x * 128;    // 2 q-items
    const int warp_m = wid >> 1;
    const int warp_n = wid & 1;

    const __half* gmat[2] = { Ahi + (size_t)by * 128 * E_, Bhi + (size_t)n0 * E_ };

    auto load_stage = [&](int ks, int buf) {
        uint32_t sb = sbase + buf * STG_BYTES;
#pragma unroll
        for (int it = 0; it < 4; it++) {
            int idx = tid + it * 256;
            int mat = idx >> 9, rem = idx & 511;
            int r = rem >> 2, chunk = rem & 3;
            const void* src = gmat[mat] + (size_t)r * E_ + ks * 32 + chunk * 8;
            uint32_t dst = sb + mat * MAT_BYTES + r * 64 + ((chunk ^ (r & 3)) << 4);
            cp16(dst, src);
        }
        CP_COMMIT();
    };

    float acc[2][8][4] = {};
    load_stage(0, 0);

    for (int ks = 0; ks < 8; ks++) {
        CP_WAIT0();
        __syncthreads();
        if (ks + 1 < 8) load_stage(ks + 1, (ks + 1) & 1);

        uint32_t sb = sbase + (ks & 1) * STG_BYTES;
        const int rA = warp_m * 32 + (lane & 15);
        const int khalf = lane >> 4;
#pragma unroll
        for (int kstep = 0; kstep < 2; kstep++) {
            uint32_t ahi[2][4], bhi[4][4];
            int chunk = kstep * 2 + khalf;
#pragma unroll
            for (int mt = 0; mt < 2; mt++) {
                int r = rA + mt * 16;
                uint32_t off = r * 64 + ((chunk ^ (r & 3)) << 4);
                ldsm_x4(ahi[mt], sb + 0 * MAT_BYTES + off);
            }
#pragma unroll
            for (int nt = 0; nt < 4; nt++) {
                int r = warp_n * 64 + nt * 16 + (lane & 15);
                uint32_t off = r * 64 + ((chunk ^ (r & 3)) << 4);
                ldsm_x4(bhi[nt], sb + 1 * MAT_BYTES + off);
            }
            // pad-skip: in-item cols 56-63 are always padding
#pragma unroll
            for (int mt = 0; mt < 2; mt++)
#pragma unroll
                for (int nt = 0; nt < 4; nt++) {
                    mma16816(acc[mt][nt * 2 + 0], ahi[mt], bhi[nt][0], bhi[nt][2]);
                    if (nt < 3)
                        mma16816(acc[mt][nt * 2 + 1], ahi[mt], bhi[nt][1], bhi[nt][3]);
                }
        }
        __syncthreads();
    }

    // ---- register epilogue ----
    const int l4 = lane & 3, l8 = lane >> 2;
    // rowmax over valid t cols per q (all 128 rows valid: M packed)
#pragma unroll
    for (int mt = 0; mt < 2; mt++)
#pragma unroll
        for (int ih = 0; ih < 2; ih++) {
            float rm = -1e30f;
#pragma unroll
            for (int nt8 = 0; nt8 < 7; nt8++)
#pragma unroll
                for (int j = 0; j < 2; j++) {
                    int ci = nt8 * 8 + l4 * 2 + j;
                    if (ci < K_) rm = fmaxf(rm, acc[mt][nt8][ih * 2 + j]);
                }
            rm = fmaxf(rm, __shfl_xor_sync(0xffffffffu, rm, 1));
            rm = fmaxf(rm, __shfl_xor_sync(0xffffffffu, rm, 2));
            if (l4 == 0) rbuf[warp_m * 32 + mt * 16 + ih * 8 + l8][warp_n] = rm;
        }
    // per-warp dual-slot colmax (32 rows span <=2 items)
    const int rw0 = by * 128 + warp_m * 32;
    const int s0b = rw0 / 50, s1b = (rw0 + 31) / 50;
    if (lane == 0 && warp_n == 0) { blids[warp_m][0] = s0b; blids[warp_m][1] = s1b; }
    int rb[2][2];
#pragma unroll
    for (int mt = 0; mt < 2; mt++)
#pragma unroll
        for (int ih = 0; ih < 2; ih++) rb[mt][ih] = (rw0 + mt * 16 + ih * 8 + l8) / 50;
#pragma unroll
    for (int s = 0; s < 2; s++) {
        int sb2 = (s == 0) ? s0b : s1b;
#pragma unroll
        for (int nt8 = 0; nt8 < 7; nt8++)
#pragma unroll
            for (int j = 0; j < 2; j++) {
                float cm = -1e30f;
#pragma unroll
                for (int mt = 0; mt < 2; mt++)
#pragma unroll
                    for (int ih = 0; ih < 2; ih++)
                        if (rb[mt][ih] == sb2) cm = fmaxf(cm, acc[mt][nt8][ih * 2 + j]);
                cm = fmaxf(cm, __shfl_xor_sync(0xffffffffu, cm, 4));
                cm = fmaxf(cm, __shfl_xor_sync(0xffffffffu, cm, 8));
                cm = fmaxf(cm, __shfl_xor_sync(0xffffffffu, cm, 16));
                if (l8 == 0) cpart[warp_m][s][warp_n * 64 + nt8 * 8 + l4 * 2 + j] = cm;
            }
    }
    __syncthreads();

    const int b_first = (by * 128) / 50;
    const int b_last  = (by * 128 + 127) / 50;
    if (tid < 8) {           // i2t partial sums per (bl, ql) — unique writer per entry
        int bl = tid >> 1, ql = tid & 1;
        int b = b_first + bl;
        if (b <= b_last) {
            int lo = 50 * b - by * 128, hi2 = lo + 50;
            if (lo < 0) lo = 0;
            if (hi2 > 128) hi2 = 128;
            float s = 0.f;
            for (int r = lo; r < hi2; r++) s += rbuf[r][ql];
            gI[((size_t)by * 4 + bl) * Q_ + (blockIdx.x * 2 + ql)] = s;
        }
    } else if (tid >= 128) { // colmax combine across warp slots + store
        int j = tid - 128;
        int t = j & 63, ql = j >> 6;
        if (t < K_) {
            int q = blockIdx.x * 2 + ql;
#pragma unroll
            for (int bl = 0; bl < 4; bl++) {
                int b = b_first + bl;
                if (b <= b_last) {
                    float gmv = -1e30f;
#pragma unroll
                    for (int wm = 0; wm < 4; wm++)
#pragma unroll
                        for (int s = 0; s < 2; s++)
                            if (blids[wm][s] == b) gmv = fmaxf(gmv, cpart[wm][s][j]);
                    gC[(((size_t)by * 4 + bl) * Q_ + q) * K_ + t] = gmv;
                }
            }
        }
    }
}

// ===== finalize: combine <=2 block partials per (b,q) -> i2t, t2i =====
__global__ void __launch_bounds__(256)
finalize_kernel(const float* __restrict__ gI, const float* __restrict__ gC,
                float* __restrict__ i2t, float* __restrict__ t2i) {
    __shared__ float s0[128][51];
    __shared__ float s1[128][51];
    int b = blockIdx.x / 3;
    int qg = (blockIdx.x % 3) * 128;
    int tid = threadIdx.x;
    int r0 = 50 * b, r1 = r0 + 49;
    int by0 = r0 >> 7, by1 = r1 >> 7;
    int bl0 = b - (by0 * 128) / 50;
    int bl1 = b - (by1 * 128) / 50;
    const float* src0 = gC + (((size_t)by0 * 4 + bl0) * Q_ + qg) * K_;
    const float* src1 = gC + (((size_t)by1 * 4 + bl1) * Q_ + qg) * K_;
    for (int i = tid; i < 128 * K_; i += 256) {
        int qq = i / K_, tt = i % K_;
        s0[qq][tt] = src0[i];
        s1[qq][tt] = (by1 != by0) ? src1[i] : src0[i];
    }
    __syncthreads();
    if (tid < 128) {
        int q = qg + tid;
        float s = gI[((size_t)by0 * 4 + bl0) * Q_ + q];
        if (by1 != by0) s += gI[((size_t)by1 * 4 + bl1) * Q_ + q];
        i2t[(size_t)b * Q_ + q] = s * (1.0f / 50.0f);
        float ts = 0.f;
        for (int t = 0; t < K_; t++) ts += fmaxf(s0[tid][t], s1[tid][t]);
        t2i[(size_t)b * Q_ + q] = ts * (1.0f / 50.0f);
    }
}

// ---------------- launch ----------------
extern "C" void kernel_launch(void* const* d_in, const int* in_sizes, int n_in,
                              void* d_out, int out_size) {
    const float* visual_cls     = (const float*)d_in[0];
    const float* visual_tokens  = (const float*)d_in[1];
    const float* textual_cls    = (const float*)d_in[2];
    const float* textual_tokens = (const float*)d_in[3];
    const float* Wv     = (const float*)d_in[4];
    const float* bv     = (const float*)d_in[5];
    const float* Wt     = (const float*)d_in[6];
    const float* bt     = (const float*)d_in[7];
    const float* Wv_tok = (const float*)d_in[8];
    const float* bv_tok = (const float*)d_in[9];
    const float* Wt_tok = (const float*)d_in[10];
    const float* bt_tok = (const float*)d_in[11];

    float* out = (float*)d_out;
    float* o_vcls = out;
    float* o_tcls = o_vcls + B_ * E_;
    float* o_vloc = o_tcls + Q_ * E_;
    float* o_tloc = o_vloc + B_ * K_ * E_;
    float* o_i2t  = o_tloc + Q_ * K_ * E_;
    float* o_t2i  = o_i2t + B_ * Q_;

    float *p_vtok, *p_ttok, *p_vglob, *p_tglob, *p_vnf, *p_tnf, *p_pI, *p_pC;
    double *p_vsim, *p_tsim;
    int *p_iv, *p_it;
    __half *p_Avh, *p_Avl, *p_Ath, *p_Atl, *p_Acvh, *p_Acvl, *p_Acth, *p_Actl;
    __half *p_Wvh, *p_Wvl, *p_Wth, *p_Wtl, *p_Wvth, *p_Wvtl, *p_Wtth, *p_Wttl;
    __half *p_vhi, *p_thi;
    cudaGetSymbolAddress((void**)&p_vtok, g_vtok);
    cudaGetSymbolAddress((void**)&p_ttok, g_ttok);
    cudaGetSymbolAddress((void**)&p_vglob, g_vglob);
    cudaGetSymbolAddress((void**)&p_tglob, g_tglob);
    cudaGetSymbolAddress((void**)&p_vsim, g_vsim);
    cudaGetSymbolAddress((void**)&p_tsim, g_tsim);
    cudaGetSymbolAddress((void**)&p_vnf, g_vnf);
    cudaGetSymbolAddress((void**)&p_tnf, g_tnf);
    cudaGetSymbolAddress((void**)&p_iv, g_iv);
    cudaGetSymbolAddress((void**)&p_it, g_it);
    cudaGetSymbolAddress((void**)&p_pI, g_pI);
    cudaGetSymbolAddress((void**)&p_pC, g_pC);
    cudaGetSymbolAddress((void**)&p_Avh, g_Avh);  cudaGetSymbolAddress((void**)&p_Avl, g_Avl);
    cudaGetSymbolAddress((void**)&p_Ath, g_Ath);  cudaGetSymbolAddress((void**)&p_Atl, g_Atl);
    cudaGetSymbolAddress((void**)&p_Acvh, g_Acvh); cudaGetSymbolAddress((void**)&p_Acvl, g_Acvl);
    cudaGetSymbolAddress((void**)&p_Acth, g_Acth); cudaGetSymbolAddress((void**)&p_Actl, g_Actl);
    cudaGetSymbolAddress((void**)&p_Wvh, g_Wvh);  cudaGetSymbolAddress((void**)&p_Wvl, g_Wvl);
    cudaGetSymbolAddress((void**)&p_Wth, g_Wth);  cudaGetSymbolAddress((void**)&p_Wtl, g_Wtl);
    cudaGetSymbolAddress((void**)&p_Wvth, g_Wvth); cudaGetSymbolAddress((void**)&p_Wvtl, g_Wvtl);
    cudaGetSymbolAddress((void**)&p_Wtth, g_Wtth); cudaGetSymbolAddress((void**)&p_Wttl, g_Wttl);
    cudaGetSymbolAddress((void**)&p_vhi, g_vhi);
    cudaGetSymbolAddress((void**)&p_thi, g_thi);

    // ---- split inputs & weights to fp16 hi/lo ----
    split_f16_kernel<<<(B_ * V_ * D_) / 256, 256>>>(visual_tokens, p_Avh, p_Avl);
    split_f16_kernel<<<(Q_ * T_ * D_) / 256, 256>>>(textual_tokens, p_Ath, p_Atl);
    split_f16_kernel<<<(B_ * D_) / 256, 256>>>(visual_cls, p_Acvh, p_Acvl);
    split_f16_kernel<<<(Q_ * D_) / 256, 256>>>(textual_cls, p_Acth, p_Actl);
    split_w_kernel<<<D_, E_>>>(Wv, p_Wvh, p_Wvl);
    split_w_kernel<<<D_, E_>>>(Wt, p_Wth, p_Wtl);
    split_w_kernel<<<D_, E_>>>(Wv_tok, p_Wvth, p_Wvtl);
    split_w_kernel<<<D_, E_>>>(Wt_tok, p_Wtth, p_Wttl);

    // ---- projections on HMMA (3-term fp16 — protects top-k ranking keys) ----
    cudaFuncSetAttribute(proj_mma_kernel, cudaFuncAttributeMaxDynamicSharedMemorySize, 2 * PSTG);
    proj_mma_kernel<<<dim3(2, B_ / 128), 256, 2 * PSTG>>>(p_Acvh, p_Acvl, p_Wvh, p_Wvl, bv, o_vcls);
    proj_mma_kernel<<<dim3(2, Q_ / 128), 256, 2 * PSTG>>>(p_Acth, p_Actl, p_Wth, p_Wtl, bt, o_tcls);
    proj_mma_kernel<<<dim3(2, (B_ * V_) / 128), 256, 2 * PSTG>>>(p_Avh, p_Avl, p_Wvth, p_Wvtl, bv_tok, p_vtok);
    proj_mma_kernel<<<dim3(2, (Q_ * T_) / 128), 256, 2 * PSTG>>>(p_Ath, p_Atl, p_Wtth, p_Wttl, bt_tok, p_ttok);

    norm_rows_kernel<<<(B_ * 32) / 256, 256>>>(o_vcls, p_vglob, B_);
    norm_rows_kernel<<<(Q_ * 32) / 256, 256>>>(o_tcls, p_tglob, Q_);

    tok_sim_kernel<<<(B_ * V_ * 32) / 256, 256>>>(p_vtok, p_vglob, p_vsim, p_vnf, B_ * V_, V_);
    tok_sim_kernel<<<(Q_ * T_ * 32) / 256, 256>>>(p_ttok, p_tglob, p_tsim, p_tnf, Q_ * T_, T_);

    topk_kernel<<<B_, 256>>>(p_vsim, p_iv, V_);
    topk_kernel<<<Q_, 256>>>(p_tsim, p_it, T_);
    gather_v_kernel<<<B_ * K_, 64>>>(p_vtok, p_vnf, p_iv, o_vloc, p_vhi, V_);
    gather_t_kernel<<<Q_ * KP, 64>>>(p_ttok, p_tnf, p_it, o_tloc, p_thi, T_);

    // ---- M-packed single-term fp16 cross sim -> partials -> finalize ----
    const int DSMEM = 2 * STG_BYTES;
    cudaFuncSetAttribute(cross_sim_mma_kernel, cudaFuncAttributeMaxDynamicSharedMemorySize, DSMEM);
    cross_sim_mma_kernel<<<dim3(Q_ / 2, NBY), 256, DSMEM>>>(p_vhi, p_thi, p_pI, p_pC);
    finalize_kernel<<<B_ * 3, 256>>>(p_pI, p_pC, o_i2t, o_t2i);
}

// round 14
// speedup vs baseline: 4.9549x; 1.0229x over previous
#include <cuda_runtime.h>
#include <cuda_fp16.h>
#include <math.h>
#include <stdint.h>

#define B_ 384
#define Q_ 384
#define V_ 197
#define T_ 100
#define D_ 768
#define E_ 256
#define K_ 50
#define KP 64
#define MR (B_ * KP)
#define MPACK (B_ * K_)
#define NBY (MPACK / 128)      // 150

// ---------------- scratch (no allocations allowed) ----------------
__device__ float  g_vtok[B_*V_*E_];
__device__ float  g_ttok[Q_*T_*E_];
__device__ float  g_glob[2*B_*E_];      // [0..384) v_cls norms, [384..768) t_cls
__device__ double g_vsim[B_*V_];
__device__ double g_tsim[Q_*T_];
__device__ float  g_vnf[B_*V_];
__device__ float  g_tnf[Q_*T_];
__device__ int    g_iv[B_*K_];
__device__ int    g_it[Q_*K_];
__device__ float  g_pI[NBY*4*Q_];
__device__ float  g_pC[(size_t)NBY*4*Q_*K_];
__device__ __align__(16) __half g_Avh[B_*V_*D_];
__device__ __align__(16) __half g_Avl[B_*V_*D_];
__device__ __align__(16) __half g_Ath[Q_*T_*D_];
__device__ __align__(16) __half g_Atl[Q_*T_*D_];
__device__ __align__(16) __half g_Acvh[B_*D_];
__device__ __align__(16) __half g_Acvl[B_*D_];
__device__ __align__(16) __half g_Acth[Q_*D_];
__device__ __align__(16) __half g_Actl[Q_*D_];
__device__ __align__(16) __half g_Wvh[E_*D_];
__device__ __align__(16) __half g_Wvl[E_*D_];
__device__ __align__(16) __half g_Wth[E_*D_];
__device__ __align__(16) __half g_Wtl[E_*D_];
__device__ __align__(16) __half g_Wvth[E_*D_];
__device__ __align__(16) __half g_Wvtl[E_*D_];
__device__ __align__(16) __half g_Wtth[E_*D_];
__device__ __align__(16) __half g_Wttl[E_*D_];
__device__ __align__(16) __half g_vhi[MR*E_];
__device__ __align__(16) __half g_thi[MR*E_];

// ================= PTX helpers =================
__device__ __forceinline__ uint32_t smem_u32(const void* p) {
    uint32_t a;
    asm("{ .reg .u64 t; cvta.to.shared.u64 t, %1; cvt.u32.u64 %0, t; }" : "=r"(a) : "l"(p));
    return a;
}
__device__ __forceinline__ void ldsm_x4(uint32_t* r, uint32_t addr) {
    asm volatile("ldmatrix.sync.aligned.m8n8.x4.shared.b16 {%0,%1,%2,%3}, [%4];"
                 : "=r"(r[0]), "=r"(r[1]), "=r"(r[2]), "=r"(r[3]) : "r"(addr));
}
__device__ __forceinline__ void mma16816(float* d, const uint32_t* a, uint32_t b0, uint32_t b1) {
    asm volatile(
        "mma.sync.aligned.m16n8k16.row.col.f32.f16.f16.f32 "
        "{%0,%1,%2,%3}, {%4,%5,%6,%7}, {%8,%9}, {%0,%1,%2,%3};"
        : "+f"(d[0]), "+f"(d[1]), "+f"(d[2]), "+f"(d[3])
        : "r"(a[0]), "r"(a[1]), "r"(a[2]), "r"(a[3]), "r"(b0), "r"(b1));
}
__device__ __forceinline__ void cp16(uint32_t dst, const void* src) {
    asm volatile("cp.async.cg.shared.global [%0], [%1], 16;" :: "r"(dst), "l"(src) : "memory");
}
#define CP_COMMIT() asm volatile("cp.async.commit_group;" ::: "memory")
#define CP_WAIT0()  asm volatile("cp.async.wait_group 0;" ::: "memory")

// ---------------- merged input split (all 4 f32 tensors -> fp16 hi/lo) ----------------
#define N_VT (B_*V_*D_)
#define N_TT (Q_*T_*D_)
#define N_VC (B_*D_)
__global__ void split_in_all(const float* __restrict__ vt, const float* __restrict__ tt,
                             const float* __restrict__ vc, const float* __restrict__ tc,
                             __half* __restrict__ vth, __half* __restrict__ vtl,
                             __half* __restrict__ tth, __half* __restrict__ ttl,
                             __half* __restrict__ vch, __half* __restrict__ vcl,
                             __half* __restrict__ tch, __half* __restrict__ tcl) {
    long i = (long)blockIdx.x * 256 + threadIdx.x;
    const float* src; __half *hi, *lo; long o;
    if (i < N_VT)                        { src = vt; hi = vth; lo = vtl; o = i; }
    else if (i < (long)N_VT + N_TT)      { src = tt; hi = tth; lo = ttl; o = i - N_VT; }
    else if (i < (long)N_VT + N_TT + N_VC) { src = vc; hi = vch; lo = vcl; o = i - N_VT - N_TT; }
    else                                 { src = tc; hi = tch; lo = tcl; o = i - N_VT - N_TT - N_VC; }
    float a = src[o];
    __half h = __float2half(a);
    hi[o] = h;
    lo[o] = __float2half(a - __half2float(h));
}

// ---------------- merged weight split + transpose (4 weights) ----------------
__global__ void split_w_all(const float* __restrict__ W0, const float* __restrict__ W1,
                            const float* __restrict__ W2, const float* __restrict__ W3,
                            __half* __restrict__ h0, __half* __restrict__ l0,
                            __half* __restrict__ h1, __half* __restrict__ l1,
                            __half* __restrict__ h2, __half* __restrict__ l2,
                            __half* __restrict__ h3, __half* __restrict__ l3) {
    int k = blockIdx.x, sel = blockIdx.y, n = threadIdx.x;
    const float* W = (sel == 0) ? W0 : (sel == 1) ? W1 : (sel == 2) ? W2 : W3;
    __half* hiT = (sel == 0) ? h0 : (sel == 1) ? h1 : (sel == 2) ? h2 : h3;
    __half* loT = (sel == 0) ? l0 : (sel == 1) ? l1 : (sel == 2) ? l2 : l3;
    float a = W[k * E_ + n];
    __half h = __float2half(a);
    hiT[n * D_ + k] = h;
    loT[n * D_ + k] = __float2half(a - __half2float(h));
}

// ================= projection GEMM on HMMA (3-term fp16) =================
#define PSTG 32768
#define PMAT 8192
__global__ void __launch_bounds__(256)
proj_mma_kernel(const __half* __restrict__ Ah, const __half* __restrict__ Al,
                const __half* __restrict__ Wh, const __half* __restrict__ Wl,
                const float* __restrict__ bias, float* __restrict__ C) {
    extern __shared__ __align__(16) char dyn[];
    const uint32_t sbase = smem_u32(dyn);
    const int tid = threadIdx.x, wid = tid >> 5, lane = tid & 31;
    const int m0 = blockIdx.y * 128, n0 = blockIdx.x * 128;
    const int warp_m = wid >> 1, warp_n = wid & 1;
    const __half* gmat[4] = { Ah + (size_t)m0 * D_, Al + (size_t)m0 * D_,
                              Wh + (size_t)n0 * D_, Wl + (size_t)n0 * D_ };
    auto load_stage = [&](int ks, int buf) {
        uint32_t sb = sbase + buf * PSTG;
#pragma unroll
        for (int it = 0; it < 8; it++) {
            int idx = tid + it * 256;
            int mat = idx >> 9, rem = idx & 511;
            int r = rem >> 2, chunk = rem & 3;
            const void* src = gmat[mat] + (size_t)r * D_ + ks * 32 + chunk * 8;
            uint32_t dst = sb + mat * PMAT + r * 64 + ((chunk ^ (r & 3)) << 4);
            cp16(dst, src);
        }
        CP_COMMIT();
    };
    float acc[2][8][4] = {};
    load_stage(0, 0);
    for (int ks = 0; ks < 24; ks++) {
        CP_WAIT0();
        __syncthreads();
        if (ks + 1 < 24) load_stage(ks + 1, (ks + 1) & 1);
        uint32_t sb = sbase + (ks & 1) * PSTG;
        const int rA = warp_m * 32 + (lane & 15);
        const int khalf = lane >> 4;
#pragma unroll
        for (int kstep = 0; kstep < 2; kstep++) {
            uint32_t ah[2][4], al[2][4], wh[4][4], wl[4][4];
            int chunk = kstep * 2 + khalf;
#pragma unroll
            for (int mt = 0; mt < 2; mt++) {
                int r = rA + mt * 16;
                uint32_t off = r * 64 + ((chunk ^ (r & 3)) << 4);
                ldsm_x4(ah[mt], sb + 0 * PMAT + off);
                ldsm_x4(al[mt], sb + 1 * PMAT + off);
            }
#pragma unroll
            for (int nt = 0; nt < 4; nt++) {
                int r = warp_n * 64 + nt * 16 + (lane & 15);
                uint32_t off = r * 64 + ((chunk ^ (r & 3)) << 4);
                ldsm_x4(wh[nt], sb + 2 * PMAT + off);
                ldsm_x4(wl[nt], sb + 3 * PMAT + off);
            }
#pragma unroll
            for (int mt = 0; mt < 2; mt++)
#pragma unroll
                for (int nt = 0; nt < 4; nt++) {
                    mma16816(acc[mt][nt * 2 + 0], ah[mt], wh[nt][0], wh[nt][2]);
                    mma16816(acc[mt][nt * 2 + 1], ah[mt], wh[nt][1], wh[nt][3]);
                    mma16816(acc[mt][nt * 2 + 0], ah[mt], wl[nt][0], wl[nt][2]);
                    mma16816(acc[mt][nt * 2 + 1], ah[mt], wl[nt][1], wl[nt][3]);
                    mma16816(acc[mt][nt * 2 + 0], al[mt], wh[nt][0], wh[nt][2]);
                    mma16816(acc[mt][nt * 2 + 1], al[mt], wh[nt][1], wh[nt][3]);
                }
        }
        __syncthreads();
    }
#pragma unroll
    for (int mt = 0; mt < 2; mt++)
#pragma unroll
        for (int nt8 = 0; nt8 < 8; nt8++) {
            int row = m0 + warp_m * 32 + mt * 16 + (lane >> 2);
            int col = n0 + warp_n * 64 + nt8 * 8 + (lane & 3) * 2;
            C[(size_t)row * E_ + col]           = acc[mt][nt8][0] + bias[col];
            C[(size_t)row * E_ + col + 1]       = acc[mt][nt8][1] + bias[col + 1];
            C[(size_t)(row + 8) * E_ + col]     = acc[mt][nt8][2] + bias[col];
            C[(size_t)(row + 8) * E_ + col + 1] = acc[mt][nt8][3] + bias[col + 1];
        }
}

// ------- l2-normalize 768 contiguous cls rows (f64 norm, f32 division) -------
__global__ void norm_rows_kernel(const float* __restrict__ in, float* __restrict__ out) {
    int warp = (blockIdx.x * blockDim.x + threadIdx.x) >> 5;
    int lane = threadIdx.x & 31;
    const float* r = in + (size_t)warp * E_;
    float v[8]; double s = 0.0;
#pragma unroll
    for (int j = 0; j < 8; j++) { v[j] = r[j * 32 + lane]; s += (double)v[j] * (double)v[j]; }
#pragma unroll
    for (int o = 16; o > 0; o >>= 1) s += __shfl_xor_sync(0xffffffffu, s, o);
    float nf = fmaxf((float)sqrt(s), 1e-12f);
#pragma unroll
    for (int j = 0; j < 8; j++) out[(size_t)warp * E_ + j * 32 + lane] = v[j] / nf;
}

// ---- merged per-row norm (f64) + f64 dot-with-global sim for BOTH modalities ----
__global__ void tok_sim_kernel(const float* __restrict__ vtok, const float* __restrict__ ttok,
                               const float* __restrict__ glob,
                               double* __restrict__ vsim, double* __restrict__ tsim,
                               float* __restrict__ vnf, float* __restrict__ tnf) {
    int warp = (blockIdx.x * blockDim.x + threadIdx.x) >> 5;
    int lane = threadIdx.x & 31;
    const float* tok; double* sim; float* nfa; int gidx;
    if (warp < B_ * V_) {
        tok = vtok + (size_t)warp * E_; sim = vsim + warp; nfa = vnf + warp; gidx = warp / V_;
    } else {
        int w = warp - B_ * V_;
        tok = ttok + (size_t)w * E_; sim = tsim + w; nfa = tnf + w; gidx = B_ + w / T_;
    }
    float v[8]; double s = 0.0;
#pragma unroll
    for (int j = 0; j < 8; j++) { v[j] = tok[j * 32 + lane]; s += (double)v[j] * (double)v[j]; }
#pragma unroll
    for (int o = 16; o > 0; o >>= 1) s += __shfl_xor_sync(0xffffffffu, s, o);
    float nf = fmaxf((float)sqrt(s), 1e-12f);
    const float* g = glob + (size_t)gidx * E_;
    double d = 0.0;
#pragma unroll
    for (int j = 0; j < 8; j++) {
        float nv = v[j] / nf;
        d += (double)nv * (double)g[j * 32 + lane];
    }
#pragma unroll
    for (int o = 16; o > 0; o >>= 1) d += __shfl_xor_sync(0xffffffffu, d, o);
    if (lane == 0) { *sim = d; *nfa = nf; }
}

// ---------------- merged top-K (both modalities) ----------------
__global__ void topk_kernel(const double* __restrict__ vsim, const double* __restrict__ tsim,
                            int* __restrict__ iv, int* __restrict__ it) {
    __shared__ double vals[256];
    __shared__ double wv[8];
    __shared__ int wi[8];
    int blk = blockIdx.x;
    const double* sim; int* out; int n;
    if (blk < B_) { sim = vsim + (size_t)blk * V_; out = iv + blk * K_; n = V_; }
    else          { int b = blk - B_; sim = tsim + (size_t)b * T_; out = it + b * K_; n = T_; }
    int t = threadIdx.x;
    vals[t] = (t < n) ? sim[t] : -1e300;
    __syncthreads();
    for (int k = 0; k < K_; k++) {
        double v = vals[t]; int i = t;
#pragma unroll
        for (int o = 16; o > 0; o >>= 1) {
            double ov = __shfl_xor_sync(0xffffffffu, v, o);
            int oi = __shfl_xor_sync(0xffffffffu, i, o);
            if (ov > v || (ov == v && oi < i)) { v = ov; i = oi; }
        }
        if ((t & 31) == 0) { wv[t >> 5] = v; wi[t >> 5] = i; }
        __syncthreads();
        if (t == 0) {
            double bv = wv[0]; int bi = wi[0];
#pragma unroll
            for (int w = 1; w < 8; w++)
                if (wv[w] > bv || (wv[w] == bv && wi[w] < bi)) { bv = wv[w]; bi = wi[w]; }
            out[k] = bi;
            vals[bi] = -1e300;
        }
        __syncthreads();
    }
}

// --- merged gather: v packed (19200 blocks) then t padded (24576 blocks) ---
__global__ void gather_all_kernel(const float* __restrict__ vtok, const float* __restrict__ vnfa,
                                  const int* __restrict__ iv, float* __restrict__ vout,
                                  __half* __restrict__ vhi,
                                  const float* __restrict__ ttok, const float* __restrict__ tnfa,
                                  const int* __restrict__ it, float* __restrict__ tout,
                                  __half* __restrict__ thi) {
    int blk = blockIdx.x;
    int t = threadIdx.x;
    if (blk < B_ * K_) {           // v: packed scratch
        int item = blk / K_, r = blk % K_;
        int src = iv[item * K_ + r];
        size_t srow = ((size_t)item * V_ + src) * E_;
        float nf = vnfa[item * V_ + src];
        float4 v = *reinterpret_cast<const float4*>(vtok + srow + t * 4);
        v.x /= nf; v.y /= nf; v.z /= nf; v.w /= nf;
        *reinterpret_cast<float4*>(vout + (size_t)blk * E_ + t * 4) = v;
        __half h[4];
        h[0] = __float2half(v.x); h[1] = __float2half(v.y);
        h[2] = __float2half(v.z); h[3] = __float2half(v.w);
        *reinterpret_cast<uint2*>(vhi + (size_t)blk * E_ + t * 4) = *reinterpret_cast<uint2*>(h);
    } else {                        // t: padded scratch (64 rows/item)
        int bk = blk - B_ * K_;
        int item = bk >> 6, r = bk & 63;
        size_t po = (size_t)(item * KP + r) * E_ + t * 4;
        if (r < K_) {
            int src = it[item * K_ + r];
            size_t srow = ((size_t)item * T_ + src) * E_;
            float nf = tnfa[item * T_ + src];
            float4 v = *reinterpret_cast<const float4*>(ttok + srow + t * 4);
            v.x /= nf; v.y /= nf; v.z /= nf; v.w /= nf;
            *reinterpret_cast<float4*>(tout + (size_t)(item * K_ + r) * E_ + t * 4) = v;
            __half h[4];
            h[0] = __float2half(v.x); h[1] = __float2half(v.y);
            h[2] = __float2half(v.z); h[3] = __float2half(v.w);
            *reinterpret_cast<uint2*>(thi + po) = *reinterpret_cast<uint2*>(h);
        } else {
            uint2 z = {0u, 0u};
            *reinterpret_cast<uint2*>(thi + po) = z;
        }
    }
}

// ===== M-packed mma.sync cross sim: partial rowsum/colmax outputs =====
#define STG_BYTES 16384
#define MAT_BYTES 8192

__global__ void __launch_bounds__(256)
cross_sim_mma_kernel(const __half* __restrict__ Ahi, const __half* __restrict__ Bhi,
                     float* __restrict__ gI, float* __restrict__ gC) {
    extern __shared__ __align__(16) char dyn[];
    __shared__ float rbuf[128][2];
    __shared__ float cpart[4][2][128];
    __shared__ int   blids[4][2];

    const uint32_t sbase = smem_u32(dyn);
    const int tid = threadIdx.x;
    const int wid = tid >> 5;
    const int lane = tid & 31;
    const int by = blockIdx.y;
    const int n0 = blockIdx.x * 128;
    const int warp_m = wid >> 1;
    const int warp_n = wid & 1;

    const __half* gmat[2] = { Ahi + (size_t)by * 128 * E_, Bhi + (size_t)n0 * E_ };

    auto load_stage = [&](int ks, int buf) {
        uint32_t sb = sbase + buf * STG_BYTES;
#pragma unroll
        for (int it = 0; it < 4; it++) {
            int idx = tid + it * 256;
            int mat = idx >> 9, rem = idx & 511;
            int r = rem >> 2, chunk = rem & 3;
            const void* src = gmat[mat] + (size_t)r * E_ + ks * 32 + chunk * 8;
            uint32_t dst = sb + mat * MAT_BYTES + r * 64 + ((chunk ^ (r & 3)) << 4);
            cp16(dst, src);
        }
        CP_COMMIT();
    };

    float acc[2][8][4] = {};
    load_stage(0, 0);

    for (int ks = 0; ks < 8; ks++) {
        CP_WAIT0();
        __syncthreads();
        if (ks + 1 < 8) load_stage(ks + 1, (ks + 1) & 1);

        uint32_t sb = sbase + (ks & 1) * STG_BYTES;
        const int rA = warp_m * 32 + (lane & 15);
        const int khalf = lane >> 4;
#pragma unroll
        for (int kstep = 0; kstep < 2; kstep++) {
            uint32_t ahi[2][4], bhi[4][4];
            int chunk = kstep * 2 + khalf;
#pragma unroll
            for (int mt = 0; mt < 2; mt++) {
                int r = rA + mt * 16;
                uint32_t off = r * 64 + ((chunk ^ (r & 3)) << 4);
                ldsm_x4(ahi[mt], sb + 0 * MAT_BYTES + off);
            }
#pragma unroll
            for (int nt = 0; nt < 4; nt++) {
                int r = warp_n * 64 + nt * 16 + (lane & 15);
                uint32_t off = r * 64 + ((chunk ^ (r & 3)) << 4);
                ldsm_x4(bhi[nt], sb + 1 * MAT_BYTES + off);
            }
#pragma unroll
            for (int mt = 0; mt < 2; mt++)
#pragma unroll
                for (int nt = 0; nt < 4; nt++) {
                    mma16816(acc[mt][nt * 2 + 0], ahi[mt], bhi[nt][0], bhi[nt][2]);
                    if (nt < 3)
                        mma16816(acc[mt][nt * 2 + 1], ahi[mt], bhi[nt][1], bhi[nt][3]);
                }
        }
        __syncthreads();
    }

    // ---- register epilogue ----
    const int l4 = lane & 3, l8 = lane >> 2;
#pragma unroll
    for (int mt = 0; mt < 2; mt++)
#pragma unroll
        for (int ih = 0; ih < 2; ih++) {
            float rm = -1e30f;
#pragma unroll
            for (int nt8 = 0; nt8 < 7; nt8++)
#pragma unroll
                for (int j = 0; j < 2; j++) {
                    int ci = nt8 * 8 + l4 * 2 + j;
                    if (ci < K_) rm = fmaxf(rm, acc[mt][nt8][ih * 2 + j]);
                }
            rm = fmaxf(rm, __shfl_xor_sync(0xffffffffu, rm, 1));
            rm = fmaxf(rm, __shfl_xor_sync(0xffffffffu, rm, 2));
            if (l4 == 0) rbuf[warp_m * 32 + mt * 16 + ih * 8 + l8][warp_n] = rm;
        }
    const int rw0 = by * 128 + warp_m * 32;
    const int s0b = rw0 / 50, s1b = (rw0 + 31) / 50;
    if (lane == 0 && warp_n == 0) { blids[warp_m][0] = s0b; blids[warp_m][1] = s1b; }
    int rb[2][2];
#pragma unroll
    for (int mt = 0; mt < 2; mt++)
#pragma unroll
        for (int ih = 0; ih < 2; ih++) rb[mt][ih] = (rw0 + mt * 16 + ih * 8 + l8) / 50;
#pragma unroll
    for (int s = 0; s < 2; s++) {
        int sb2 = (s == 0) ? s0b : s1b;
#pragma unroll
        for (int nt8 = 0; nt8 < 7; nt8++)
#pragma unroll
            for (int j = 0; j < 2; j++) {
                float cm = -1e30f;
#pragma unroll
                for (int mt = 0; mt < 2; mt++)
#pragma unroll
                    for (int ih = 0; ih < 2; ih++)
                        if (rb[mt][ih] == sb2) cm = fmaxf(cm, acc[mt][nt8][ih * 2 + j]);
                cm = fmaxf(cm, __shfl_xor_sync(0xffffffffu, cm, 4));
                cm = fmaxf(cm, __shfl_xor_sync(0xffffffffu, cm, 8));
                cm = fmaxf(cm, __shfl_xor_sync(0xffffffffu, cm, 16));
                if (l8 == 0) cpart[warp_m][s][warp_n * 64 + nt8 * 8 + l4 * 2 + j] = cm;
            }
    }
    __syncthreads();

    const int b_first = (by * 128) / 50;
    const int b_last  = (by * 128 + 127) / 50;
    if (tid < 8) {
        int bl = tid >> 1, ql = tid & 1;
        int b = b_first + bl;
        if (b <= b_last) {
            int lo = 50 * b - by * 128, hi2 = lo + 50;
            if (lo < 0) lo = 0;
            if (hi2 > 128) hi2 = 128;
            float s = 0.f;
            for (int r = lo; r < hi2; r++) s += rbuf[r][ql];
            gI[((size_t)by * 4 + bl) * Q_ + (blockIdx.x * 2 + ql)] = s;
        }
    } else if (tid >= 128) {
        int j = tid - 128;
        int t = j & 63, ql = j >> 6;
        if (t < K_) {
            int q = blockIdx.x * 2 + ql;
#pragma unroll
            for (int bl = 0; bl < 4; bl++) {
                int b = b_first + bl;
                if (b <= b_last) {
                    float gmv = -1e30f;
#pragma unroll
                    for (int wm = 0; wm < 4; wm++)
#pragma unroll
                        for (int s = 0; s < 2; s++)
                            if (blids[wm][s] == b) gmv = fmaxf(gmv, cpart[wm][s][j]);
                    gC[(((size_t)by * 4 + bl) * Q_ + q) * K_ + t] = gmv;
                }
            }
        }
    }
}

// ===== finalize: combine <=2 block partials per (b,q) -> i2t, t2i =====
__global__ void __launch_bounds__(256)
finalize_kernel(const float* __restrict__ gI, const float* __restrict__ gC,
                float* __restrict__ i2t, float* __restrict__ t2i) {
    __shared__ float s0[128][51];
    __shared__ float s1[128][51];
    int b = blockIdx.x / 3;
    int qg = (blockIdx.x % 3) * 128;
    int tid = threadIdx.x;
    int r0 = 50 * b, r1 = r0 + 49;
    int by0 = r0 >> 7, by1 = r1 >> 7;
    int bl0 = b - (by0 * 128) / 50;
    int bl1 = b - (by1 * 128) / 50;
    const float* src0 = gC + (((size_t)by0 * 4 + bl0) * Q_ + qg) * K_;
    const float* src1 = gC + (((size_t)by1 * 4 + bl1) * Q_ + qg) * K_;
    for (int i = tid; i < 128 * K_; i += 256) {
        int qq = i / K_, tt = i % K_;
        s0[qq][tt] = src0[i];
        s1[qq][tt] = (by1 != by0) ? src1[i] : src0[i];
    }
    __syncthreads();
    if (tid < 128) {
        int q = qg + tid;
        float s = gI[((size_t)by0 * 4 + bl0) * Q_ + q];
        if (by1 != by0) s += gI[((size_t)by1 * 4 + bl1) * Q_ + q];
        i2t[(size_t)b * Q_ + q] = s * (1.0f / 50.0f);
        float ts = 0.f;
        for (int t = 0; t < K_; t++) ts += fmaxf(s0[tid][t], s1[tid][t]);
        t2i[(size_t)b * Q_ + q] = ts * (1.0f / 50.0f);
    }
}

// ---------------- launch ----------------
extern "C" void kernel_launch(void* const* d_in, const int* in_sizes, int n_in,
                              void* d_out, int out_size) {
    const float* visual_cls     = (const float*)d_in[0];
    const float* visual_tokens  = (const float*)d_in[1];
    const float* textual_cls    = (const float*)d_in[2];
    const float* textual_tokens = (const float*)d_in[3];
    const float* Wv     = (const float*)d_in[4];
    const float* bv     = (const float*)d_in[5];
    const float* Wt     = (const float*)d_in[6];
    const float* bt     = (const float*)d_in[7];
    const float* Wv_tok = (const float*)d_in[8];
    const float* bv_tok = (const float*)d_in[9];
    const float* Wt_tok = (const float*)d_in[10];
    const float* bt_tok = (const float*)d_in[11];

    float* out = (float*)d_out;
    float* o_vcls = out;
    float* o_tcls = o_vcls + B_ * E_;
    float* o_vloc = o_tcls + Q_ * E_;
    float* o_tloc = o_vloc + B_ * K_ * E_;
    float* o_i2t  = o_tloc + Q_ * K_ * E_;
    float* o_t2i  = o_i2t + B_ * Q_;

    float *p_vtok, *p_ttok, *p_glob, *p_vnf, *p_tnf, *p_pI, *p_pC;
    double *p_vsim, *p_tsim;
    int *p_iv, *p_it;
    __half *p_Avh, *p_Avl, *p_Ath, *p_Atl, *p_Acvh, *p_Acvl, *p_Acth, *p_Actl;
    __half *p_Wvh, *p_Wvl, *p_Wth, *p_Wtl, *p_Wvth, *p_Wvtl, *p_Wtth, *p_Wttl;
    __half *p_vhi, *p_thi;
    cudaGetSymbolAddress((void**)&p_vtok, g_vtok);
    cudaGetSymbolAddress((void**)&p_ttok, g_ttok);
    cudaGetSymbolAddress((void**)&p_glob, g_glob);
    cudaGetSymbolAddress((void**)&p_vsim, g_vsim);
    cudaGetSymbolAddress((void**)&p_tsim, g_tsim);
    cudaGetSymbolAddress((void**)&p_vnf, g_vnf);
    cudaGetSymbolAddress((void**)&p_tnf, g_tnf);
    cudaGetSymbolAddress((void**)&p_iv, g_iv);
    cudaGetSymbolAddress((void**)&p_it, g_it);
    cudaGetSymbolAddress((void**)&p_pI, g_pI);
    cudaGetSymbolAddress((void**)&p_pC, g_pC);
    cudaGetSymbolAddress((void**)&p_Avh, g_Avh);  cudaGetSymbolAddress((void**)&p_Avl, g_Avl);
    cudaGetSymbolAddress((void**)&p_Ath, g_Ath);  cudaGetSymbolAddress((void**)&p_Atl, g_Atl);
    cudaGetSymbolAddress((void**)&p_Acvh, g_Acvh); cudaGetSymbolAddress((void**)&p_Acvl, g_Acvl);
    cudaGetSymbolAddress((void**)&p_Acth, g_Acth); cudaGetSymbolAddress((void**)&p_Actl, g_Actl);
    cudaGetSymbolAddress((void**)&p_Wvh, g_Wvh);  cudaGetSymbolAddress((void**)&p_Wvl, g_Wvl);
    cudaGetSymbolAddress((void**)&p_Wth, g_Wth);  cudaGetSymbolAddress((void**)&p_Wtl, g_Wtl);
    cudaGetSymbolAddress((void**)&p_Wvth, g_Wvth); cudaGetSymbolAddress((void**)&p_Wvtl, g_Wvtl);
    cudaGetSymbolAddress((void**)&p_Wtth, g_Wtth); cudaGetSymbolAddress((void**)&p_Wttl, g_Wttl);
    cudaGetSymbolAddress((void**)&p_vhi, g_vhi);
    cudaGetSymbolAddress((void**)&p_thi, g_thi);

    // ---- merged splits ----
    const long NTOT = (long)N_VT + N_TT + 2 * N_VC;
    split_in_all<<<(unsigned)(NTOT / 256), 256>>>(
        visual_tokens, textual_tokens, visual_cls, textual_cls,
        p_Avh, p_Avl, p_Ath, p_Atl, p_Acvh, p_Acvl, p_Acth, p_Actl);
    split_w_all<<<dim3(D_, 4), E_>>>(Wv, Wt, Wv_tok, Wt_tok,
                                     p_Wvh, p_Wvl, p_Wth, p_Wtl,
                                     p_Wvth, p_Wvtl, p_Wtth, p_Wttl);

    // ---- projections on HMMA (3-term fp16) ----
    cudaFuncSetAttribute(proj_mma_kernel, cudaFuncAttributeMaxDynamicSharedMemorySize, 2 * PSTG);
    proj_mma_kernel<<<dim3(2, B_ / 128), 256, 2 * PSTG>>>(p_Acvh, p_Acvl, p_Wvh, p_Wvl, bv, o_vcls);
    proj_mma_kernel<<<dim3(2, Q_ / 128), 256, 2 * PSTG>>>(p_Acth, p_Actl, p_Wth, p_Wtl, bt, o_tcls);
    proj_mma_kernel<<<dim3(2, (B_ * V_) / 128), 256, 2 * PSTG>>>(p_Avh, p_Avl, p_Wvth, p_Wvtl, bv_tok, p_vtok);
    proj_mma_kernel<<<dim3(2, (Q_ * T_) / 128), 256, 2 * PSTG>>>(p_Ath, p_Atl, p_Wtth, p_Wttl, bt_tok, p_ttok);

    // cls norms: v_cls/t_cls rows are contiguous in d_out -> one launch
    norm_rows_kernel<<<(2 * B_ * 32) / 256, 256>>>(o_vcls, p_glob);

    // merged token sims (both modalities)
    tok_sim_kernel<<<((B_ * V_ + Q_ * T_) * 32) / 256, 256>>>(
        p_vtok, p_ttok, p_glob, p_vsim, p_tsim, p_vnf, p_tnf);

    topk_kernel<<<2 * B_, 256>>>(p_vsim, p_tsim, p_iv, p_it);
    gather_all_kernel<<<B_ * K_ + Q_ * KP, 64>>>(p_vtok, p_vnf, p_iv, o_vloc, p_vhi,
                                                 p_ttok, p_tnf, p_it, o_tloc, p_thi);

    // ---- M-packed single-term fp16 cross sim -> partials -> finalize ----
    const int DSMEM = 2 * STG_BYTES;
    cudaFuncSetAttribute(cross_sim_mma_kernel, cudaFuncAttributeMaxDynamicSharedMemorySize, DSMEM);
    cross_sim_mma_kernel<<<dim3(Q_ / 2, NBY), 256, DSMEM>>>(p_vhi, p_thi, p_pI, p_pC);
    finalize_kernel<<<B_ * 3, 256>>>(p_pI, p_pC, o_i2t, o_t2i);
}